// round 4
// baseline (speedup 1.0000x reference)
#include <cuda_runtime.h>
#include <float.h>

#define NTOK   4096
#define DMODEL 320
#define HEADS  8
#define DH     40
#define NPHASE 3
#define QBLK   64        // queries per attention block
#define KT     64        // keys per attention tile
#define MAXBLK 80

// ---------------- scratch (__device__ globals; no allocation allowed) -------
__device__ float g_q[HEADS * NTOK * DH];
__device__ float g_k[HEADS * NTOK * DH];
__device__ float g_v[HEADS * NTOK * DH];
__device__ float g_o[NTOK * DMODEL];
__device__ unsigned g_mb[NPHASE * (NTOK / 32)];

// planning data
__device__ int g_grp_cnt[8], g_grp_off[8];
__device__ int g_qidx[NTOK];
__device__ int g_kcnt[8];
__device__ int g_kidx[8][NTOK];
__device__ int g_bmap_sig[MAXBLK], g_bmap_qoff[MAXBLK], g_bmap_qend[MAXBLK];
__device__ int g_nblocks;

// compacted K/V: [sig-1][head][jc][40]
__device__ float g_kc[7 * HEADS * NTOK * DH];
__device__ float g_vc[7 * HEADS * NTOK * DH];
__device__ float g_meanv[HEADS * DH];

typedef unsigned long long ull;

#define FMA2(d, a, b, c) \
    asm("fma.rn.f32x2 %0, %1, %2, %3;" : "=l"(d) : "l"(a), "l"(b), "l"(c))
#define MUL2(d, a, b) \
    asm("mul.rn.f32x2 %0, %1, %2;" : "=l"(d) : "l"(a), "l"(b))
#define PACK2(d, lo, hi) \
    asm("mov.b64 %0, {%1, %2};" : "=l"(d) : "f"(lo), "f"(hi))
#define UNPACK2(lo, hi, v) \
    asm("mov.b64 {%0, %1}, %2;" : "=f"(lo), "=f"(hi) : "l"(v))

// ---------------------------------------------------------------------------
// Pack guidance mask into bitwords
// ---------------------------------------------------------------------------
__global__ void mask_kernel(const float* __restrict__ gm) {
    int w = blockIdx.x * blockDim.x + threadIdx.x;
    if (w < NPHASE * (NTOK / 32)) {
        unsigned bits = 0;
        #pragma unroll 8
        for (int b = 0; b < 32; b++)
            if (gm[w * 32 + b] != 0.0f) bits |= (1u << b);
        g_mb[w] = bits;
    }
}

// ---------------------------------------------------------------------------
// Plan kernel (deterministic scan-based grouping)
// ---------------------------------------------------------------------------
__global__ __launch_bounds__(256) void plan_kernel() {
    __shared__ int sq[8][256];
    __shared__ int sk[8][256];
    __shared__ int base_q[8];
    const int t = threadIdx.x;

    unsigned bits_arr[16];
    int cq[8], ck[8];
    #pragma unroll
    for (int s = 0; s < 8; s++) { cq[s] = 0; ck[s] = 0; }

    for (int u = 0; u < 16; u++) {
        int i = t * 16 + u;
        unsigned b = 0;
        #pragma unroll
        for (int p = 0; p < NPHASE; p++)
            b |= ((g_mb[p * 128 + (i >> 5)] >> (i & 31)) & 1u) << p;
        bits_arr[u] = b;
        cq[b]++;
        #pragma unroll
        for (int s = 1; s < 8; s++)
            if (b & (unsigned)s) ck[s]++;
    }
    #pragma unroll
    for (int s = 0; s < 8; s++) { sq[s][t] = cq[s]; sk[s][t] = ck[s]; }
    __syncthreads();

    for (int g = 0; g < 15; g++) {
        int* arr = (g < 8) ? sq[g] : sk[g - 7];
        for (int off = 1; off < 256; off <<= 1) {
            int u = (t >= off) ? arr[t - off] : 0;
            __syncthreads();
            arr[t] += u;
            __syncthreads();
        }
    }

    if (t == 0) {
        int acc = 0;
        for (int s = 0; s < 8; s++) {
            base_q[s] = acc;
            g_grp_off[s] = acc;
            int tot = sq[s][255];
            g_grp_cnt[s] = tot;
            acc += tot;
        }
        for (int s = 1; s < 8; s++) g_kcnt[s] = sk[s][255];
        int nb = 0;
        for (int s = 1; s < 8; s++) {
            int cnt = sq[s][255], off = base_q[s];
            for (int b = 0; b * QBLK < cnt; b++) {
                g_bmap_sig[nb] = s;
                g_bmap_qoff[nb] = off + b * QBLK;
                g_bmap_qend[nb] = off + cnt;
                nb++;
            }
        }
        g_nblocks = nb;
    }
    __syncthreads();

    int qcur[8], kcur[8];
    #pragma unroll
    for (int s = 0; s < 8; s++) {
        qcur[s] = base_q[s] + sq[s][t] - cq[s];
        kcur[s] = sk[s][t] - ck[s];
    }
    for (int u = 0; u < 16; u++) {
        int i = t * 16 + u;
        unsigned b = bits_arr[u];
        g_qidx[qcur[b]++] = i;
        #pragma unroll
        for (int s = 1; s < 8; s++)
            if (b & (unsigned)s) g_kidx[s][kcur[s]++] = i;
    }
}

// ---------------------------------------------------------------------------
// QKV projection (unchanged)
// ---------------------------------------------------------------------------
__global__ __launch_bounds__(256) void qkv_gemm(
    const float* __restrict__ X,
    const float* __restrict__ Wq, const float* __restrict__ Wk,
    const float* __restrict__ Wv)
{
    const float* W = (blockIdx.z == 0) ? Wq : (blockIdx.z == 1) ? Wk : Wv;
    float* Dst = (blockIdx.z == 0) ? g_q : (blockIdx.z == 1) ? g_k : g_v;

    __shared__ float As[16][64];
    __shared__ float Bs[16][64];

    const int tid = threadIdx.x;
    const int m0 = blockIdx.y * 64;
    const int n0 = blockIdx.x * 64;
    const int tx = tid % 16, ty = tid / 16;
    const int arow = tid / 4,  acol = (tid % 4) * 4;
    const int brow = tid / 16, bcol = (tid % 16) * 4;

    float acc[4][4];
    #pragma unroll
    for (int i = 0; i < 4; i++)
        #pragma unroll
        for (int j = 0; j < 4; j++) acc[i][j] = 0.0f;

    for (int k0 = 0; k0 < DMODEL; k0 += 16) {
        float4 av = *(const float4*)(X + (size_t)(m0 + arow) * DMODEL + k0 + acol);
        float4 bv = *(const float4*)(W + (size_t)(k0 + brow) * DMODEL + n0 + bcol);
        __syncthreads();
        As[acol + 0][arow] = av.x;
        As[acol + 1][arow] = av.y;
        As[acol + 2][arow] = av.z;
        As[acol + 3][arow] = av.w;
        *(float4*)&Bs[brow][bcol] = bv;
        __syncthreads();
        #pragma unroll
        for (int kk = 0; kk < 16; kk++) {
            float4 a = *(const float4*)&As[kk][ty * 4];
            float4 b = *(const float4*)&Bs[kk][tx * 4];
            float ar[4] = {a.x, a.y, a.z, a.w};
            float br[4] = {b.x, b.y, b.z, b.w};
            #pragma unroll
            for (int i = 0; i < 4; i++)
                #pragma unroll
                for (int j = 0; j < 4; j++)
                    acc[i][j] += ar[i] * br[j];
        }
    }

    #pragma unroll
    for (int i = 0; i < 4; i++) {
        int tok = m0 + ty * 4 + i;
        #pragma unroll
        for (int j = 0; j < 4; j++) {
            int hc = n0 + tx * 4 + j;
            int h = hc / DH, d = hc % DH;
            Dst[(size_t)h * NTOK * DH + (size_t)tok * DH + d] = acc[i][j];
        }
    }
}

// ---------------------------------------------------------------------------
// Gather compacted K/V; zero-pad to multiple of KT rows.
// ---------------------------------------------------------------------------
__global__ __launch_bounds__(320) void gather_kernel() {
    const int sig = blockIdx.y + 1;
    const int head = blockIdx.z;
    const int kc = g_kcnt[sig];
    const int pad = (kc + KT - 1) & ~(KT - 1);
    const int jc = blockIdx.x * 32 + threadIdx.x / 10;
    const int c4 = threadIdx.x % 10;
    if (jc >= pad) return;

    size_t dst = ((size_t)((sig - 1) * HEADS + head) * NTOK + jc) * DH + c4 * 4;
    float4 kv = make_float4(0.f, 0.f, 0.f, 0.f);
    float4 vv = make_float4(0.f, 0.f, 0.f, 0.f);
    if (jc < kc) {
        int j = g_kidx[sig][jc];
        size_t src = ((size_t)head * NTOK + j) * DH + c4 * 4;
        kv = *(const float4*)(g_k + src);
        vv = *(const float4*)(g_v + src);
    }
    *(float4*)(g_kc + dst) = kv;
    *(float4*)(g_vc + dst) = vv;
}

// ---------------------------------------------------------------------------
// Per-head V column mean (for fully-masked rows)
// ---------------------------------------------------------------------------
__global__ __launch_bounds__(320) void meanv_kernel() {
    __shared__ float red[320];
    const int head = blockIdx.x;
    const int t = threadIdx.x;
    const int d = t % DH, r = t / DH;
    float s = 0.0f;
    for (int j = r; j < NTOK; j += 8)
        s += g_v[((size_t)head * NTOK + j) * DH + d];
    red[t] = s;
    __syncthreads();
    if (r == 0) {
        float tot = 0.0f;
        #pragma unroll
        for (int rr = 0; rr < 8; rr++) tot += red[rr * DH + d];
        g_meanv[head * DH + d] = tot * (1.0f / (float)NTOK);
    }
}

// ---------------------------------------------------------------------------
// Fill g_o rows for signature-0 queries with meanV
// ---------------------------------------------------------------------------
__global__ __launch_bounds__(256) void fill_kernel() {
    __shared__ float mv[DMODEL];
    const int t = threadIdx.x;
    for (int i = t; i < DMODEL; i += 256) mv[i] = g_meanv[i];
    __syncthreads();
    const int cnt = g_grp_cnt[0], off = g_grp_off[0];
    const int ql = blockIdx.x * 32 + t / 8;
    if (ql >= cnt) return;
    const int qi = g_qidx[off + ql];
    const int c = t % 8;
    float4* dst = (float4*)(g_o + (size_t)qi * DMODEL);
    const float4* src = (const float4*)mv;
    #pragma unroll
    for (int k = c; k < DMODEL / 4; k += 8) dst[k] = src[k];
}

// ---------------------------------------------------------------------------
// Block-flash attention with packed f32x2 FMA.
// 128 threads, 64 queries x 64-key tiles.
// Phase 1: scores, 4q x 8k register tile (keys pair-packed).
// Phase 2: P*V,    2q x 10d register tile (pairs across j).
// ---------------------------------------------------------------------------
__global__ __launch_bounds__(128) void attn_kernel() {
    if (blockIdx.x >= g_nblocks) return;

    __shared__ float  Qs [DH][QBLK];        // 40 x 64 (scaled)
    __shared__ float2 Ks2[DH][KT / 2];      // dim-major, keys packed in pairs
    __shared__ float2 Vt2[DH][KT / 2];      // dim-major, j-pairs packed
    __shared__ float2 Pt2[KT / 2][QBLK];    // [j-pair][query] = {P[q][2jp],P[q][2jp+1]}
    __shared__ float  sm_m[QBLK], sm_l[QBLK], sm_corr[QBLK];

    const int tid  = threadIdx.x;
    const int head = blockIdx.y;
    const int sig  = g_bmap_sig[blockIdx.x];
    const int qoff = g_bmap_qoff[blockIdx.x];
    const int qend = g_bmap_qend[blockIdx.x];
    const int n_k  = g_kcnt[sig];
    const float scale = 0.15811388300841898f;   // 40^-0.5

    const float* Kb = g_kc + (size_t)((sig - 1) * HEADS + head) * NTOK * DH;
    const float* Vb = g_vc + (size_t)((sig - 1) * HEADS + head) * NTOK * DH;

    // phase-1 map: ty1 -> 4 queries, tx1 -> 8 keys (4 pairs)
    const int ty1 = tid >> 3;
    const int tx1 = tid & 7;
    // phase-2 map: ty2 -> 2 queries, tx2 -> 10 dims
    const int ty2 = tid >> 2;
    const int tx2 = tid & 3;

    // load Q tile (scaled) into Qs[d][q]
    for (int idx = tid; idx < QBLK * 10; idx += 128) {
        int q = idx / 10, c4 = idx % 10;
        int ql = qoff + q;
        int qi = g_qidx[ql < qend ? ql : qoff];
        float4 v = *(const float4*)(g_q + ((size_t)head * NTOK + qi) * DH + c4 * 4);
        Qs[c4 * 4 + 0][q] = v.x * scale;
        Qs[c4 * 4 + 1][q] = v.y * scale;
        Qs[c4 * 4 + 2][q] = v.z * scale;
        Qs[c4 * 4 + 3][q] = v.w * scale;
    }
    if (tid < QBLK) { sm_m[tid] = -FLT_MAX; sm_l[tid] = 0.0f; }

    ull acc2[2][10];
    #pragma unroll
    for (int i = 0; i < 2; i++)
        #pragma unroll
        for (int dd = 0; dd < 10; dd++) acc2[i][dd] = 0ull;

    for (int t0 = 0; t0 < n_k; t0 += KT) {
        __syncthreads();   // prior-tile Pt2/Ks2/Vt2 reads done; Qs ready (1st iter)

        // load K/V tile -> dim-major pair-packed shared
        for (int idx = tid; idx < KT * 10; idx += 128) {
            int r = idx / 10, c4 = idx % 10;
            float4 kv = *(const float4*)(Kb + (size_t)(t0 + r) * DH + c4 * 4);
            float4 vv = *(const float4*)(Vb + (size_t)(t0 + r) * DH + c4 * 4);
            int jp = r >> 1, lh = r & 1;
            ((float*)&Ks2[c4 * 4 + 0][jp])[lh] = kv.x;
            ((float*)&Ks2[c4 * 4 + 1][jp])[lh] = kv.y;
            ((float*)&Ks2[c4 * 4 + 2][jp])[lh] = kv.z;
            ((float*)&Ks2[c4 * 4 + 3][jp])[lh] = kv.w;
            ((float*)&Vt2[c4 * 4 + 0][jp])[lh] = vv.x;
            ((float*)&Vt2[c4 * 4 + 1][jp])[lh] = vv.y;
            ((float*)&Vt2[c4 * 4 + 2][jp])[lh] = vv.z;
            ((float*)&Vt2[c4 * 4 + 3][jp])[lh] = vv.w;
        }
        __syncthreads();

        // ---- phase 1: scores (packed over key pairs) ----
        ull s2[4][4];
        #pragma unroll
        for (int i = 0; i < 4; i++)
            #pragma unroll
            for (int j = 0; j < 4; j++) s2[i][j] = 0ull;

        #pragma unroll 8
        for (int kk = 0; kk < DH; kk++) {
            float4 qv = *(const float4*)&Qs[kk][ty1 * 4];
            ulonglong2 ka = *(const ulonglong2*)&Ks2[kk][tx1 * 4];
            ulonglong2 kb = *(const ulonglong2*)&Ks2[kk][tx1 * 4 + 2];
            ull qq0, qq1, qq2, qq3;
            PACK2(qq0, qv.x, qv.x);
            PACK2(qq1, qv.y, qv.y);
            PACK2(qq2, qv.z, qv.z);
            PACK2(qq3, qv.w, qv.w);
            FMA2(s2[0][0], qq0, ka.x, s2[0][0]);
            FMA2(s2[0][1], qq0, ka.y, s2[0][1]);
            FMA2(s2[0][2], qq0, kb.x, s2[0][2]);
            FMA2(s2[0][3], qq0, kb.y, s2[0][3]);
            FMA2(s2[1][0], qq1, ka.x, s2[1][0]);
            FMA2(s2[1][1], qq1, ka.y, s2[1][1]);
            FMA2(s2[1][2], qq1, kb.x, s2[1][2]);
            FMA2(s2[1][3], qq1, kb.y, s2[1][3]);
            FMA2(s2[2][0], qq2, ka.x, s2[2][0]);
            FMA2(s2[2][1], qq2, ka.y, s2[2][1]);
            FMA2(s2[2][2], qq2, kb.x, s2[2][2]);
            FMA2(s2[2][3], qq2, kb.y, s2[2][3]);
            FMA2(s2[3][0], qq3, ka.x, s2[3][0]);
            FMA2(s2[3][1], qq3, ka.y, s2[3][1]);
            FMA2(s2[3][2], qq3, kb.x, s2[3][2]);
            FMA2(s2[3][3], qq3, kb.y, s2[3][3]);
        }

        // unpack, mask pad keys, softmax bookkeeping
        const int kbase = t0 + tx1 * 8;
        #pragma unroll
        for (int i = 0; i < 4; i++) {
            float s[8];
            #pragma unroll
            for (int jp = 0; jp < 4; jp++)
                UNPACK2(s[2 * jp], s[2 * jp + 1], s2[i][jp]);
            #pragma unroll
            for (int j = 0; j < 8; j++)
                if (kbase + j >= n_k) s[j] = -FLT_MAX;

            float mx = s[0];
            #pragma unroll
            for (int j = 1; j < 8; j++) mx = fmaxf(mx, s[j]);
            mx = fmaxf(mx, __shfl_xor_sync(0xffffffffu, mx, 4, 8));
            mx = fmaxf(mx, __shfl_xor_sync(0xffffffffu, mx, 2, 8));
            mx = fmaxf(mx, __shfl_xor_sync(0xffffffffu, mx, 1, 8));

            const int q = ty1 * 4 + i;
            float m_old = sm_m[q];
            float mnew = fmaxf(m_old, mx);
            float corr = __expf(m_old - mnew);

            float ps = 0.0f;
            float p[8];
            #pragma unroll
            for (int j = 0; j < 8; j++) {
                p[j] = __expf(s[j] - mnew);
                ps += p[j];
            }
            ps += __shfl_xor_sync(0xffffffffu, ps, 4, 8);
            ps += __shfl_xor_sync(0xffffffffu, ps, 2, 8);
            ps += __shfl_xor_sync(0xffffffffu, ps, 1, 8);

            #pragma unroll
            for (int jp = 0; jp < 4; jp++)
                Pt2[tx1 * 4 + jp][q] = make_float2(p[2 * jp], p[2 * jp + 1]);

            if (tx1 == 0) {
                sm_m[q] = mnew;
                sm_corr[q] = corr;
                sm_l[q] = sm_l[q] * corr + ps;
            }
        }
        __syncthreads();

        // ---- phase 2: rescale + P*V (packed over j pairs) ----
        {
            ull cc0, cc1;
            float c0 = sm_corr[ty2 * 2], c1 = sm_corr[ty2 * 2 + 1];
            PACK2(cc0, c0, c0);
            PACK2(cc1, c1, c1);
            #pragma unroll
            for (int dd = 0; dd < 10; dd++) {
                MUL2(acc2[0][dd], acc2[0][dd], cc0);
                MUL2(acc2[1][dd], acc2[1][dd], cc1);
            }
        }
        #pragma unroll 4
        for (int jp = 0; jp < KT / 2; jp++) {
            ulonglong2 pp = *(const ulonglong2*)&Pt2[jp][ty2 * 2];
            ull v0 = *(const ull*)&Vt2[tx2 * 10 + 0][jp];
            ull v1 = *(const ull*)&Vt2[tx2 * 10 + 1][jp];
            ull v2 = *(const ull*)&Vt2[tx2 * 10 + 2][jp];
            ull v3 = *(const ull*)&Vt2[tx2 * 10 + 3][jp];
            ull v4 = *(const ull*)&Vt2[tx2 * 10 + 4][jp];
            FMA2(acc2[0][0], pp.x, v0, acc2[0][0]);
            FMA2(acc2[1][0], pp.y, v0, acc2[1][0]);
            FMA2(acc2[0][1], pp.x, v1, acc2[0][1]);
            FMA2(acc2[1][1], pp.y, v1, acc2[1][1]);
            FMA2(acc2[0][2], pp.x, v2, acc2[0][2]);
            FMA2(acc2[1][2], pp.y, v2, acc2[1][2]);
            FMA2(acc2[0][3], pp.x, v3, acc2[0][3]);
            FMA2(acc2[1][3], pp.y, v3, acc2[1][3]);
            FMA2(acc2[0][4], pp.x, v4, acc2[0][4]);
            FMA2(acc2[1][4], pp.y, v4, acc2[1][4]);
            ull v5 = *(const ull*)&Vt2[tx2 * 10 + 5][jp];
            ull v6 = *(const ull*)&Vt2[tx2 * 10 + 6][jp];
            ull v7 = *(const ull*)&Vt2[tx2 * 10 + 7][jp];
            ull v8 = *(const ull*)&Vt2[tx2 * 10 + 8][jp];
            ull v9 = *(const ull*)&Vt2[tx2 * 10 + 9][jp];
            FMA2(acc2[0][5], pp.x, v5, acc2[0][5]);
            FMA2(acc2[1][5], pp.y, v5, acc2[1][5]);
            FMA2(acc2[0][6], pp.x, v6, acc2[0][6]);
            FMA2(acc2[1][6], pp.y, v6, acc2[1][6]);
            FMA2(acc2[0][7], pp.x, v7, acc2[0][7]);
            FMA2(acc2[1][7], pp.y, v7, acc2[1][7]);
            FMA2(acc2[0][8], pp.x, v8, acc2[0][8]);
            FMA2(acc2[1][8], pp.y, v8, acc2[1][8]);
            FMA2(acc2[0][9], pp.x, v9, acc2[0][9]);
            FMA2(acc2[1][9], pp.y, v9, acc2[1][9]);
        }
    }

    // epilogue: combine halves, normalize, write
    #pragma unroll
    for (int i = 0; i < 2; i++) {
        int q = ty2 * 2 + i;
        int ql = qoff + q;
        if (ql < qend) {
            int qi = g_qidx[ql];
            float inv = 1.0f / sm_l[q];
            float* op = g_o + (size_t)qi * DMODEL + head * DH + tx2 * 10;
            #pragma unroll
            for (int dd = 0; dd < 10; dd++) {
                float lo, hi;
                UNPACK2(lo, hi, acc2[i][dd]);
                op[dd] = (lo + hi) * inv;
            }
        }
    }
}

// ---------------------------------------------------------------------------
// Output projection (unchanged)
// ---------------------------------------------------------------------------
__global__ __launch_bounds__(256) void out_gemm(
    const float* __restrict__ Wo, const float* __restrict__ bo,
    float* __restrict__ out)
{
    __shared__ float As[16][64];
    __shared__ float Bs[16][64];

    const int tid = threadIdx.x;
    const int m0 = blockIdx.y * 64;
    const int n0 = blockIdx.x * 64;
    const int tx = tid % 16, ty = tid / 16;
    const int arow = tid / 4,  acol = (tid % 4) * 4;
    const int brow = tid / 16, bcol = (tid % 16) * 4;

    float acc[4][4];
    #pragma unroll
    for (int i = 0; i < 4; i++)
        #pragma unroll
        for (int j = 0; j < 4; j++) acc[i][j] = 0.0f;

    for (int k0 = 0; k0 < DMODEL; k0 += 16) {
        float4 av = *(const float4*)(g_o + (size_t)(m0 + arow) * DMODEL + k0 + acol);
        float4 bv = *(const float4*)(Wo + (size_t)(k0 + brow) * DMODEL + n0 + bcol);
        __syncthreads();
        As[acol + 0][arow] = av.x;
        As[acol + 1][arow] = av.y;
        As[acol + 2][arow] = av.z;
        As[acol + 3][arow] = av.w;
        *(float4*)&Bs[brow][bcol] = bv;
        __syncthreads();
        #pragma unroll
        for (int kk = 0; kk < 16; kk++) {
            float4 a = *(const float4*)&As[kk][ty * 4];
            float4 b = *(const float4*)&Bs[kk][tx * 4];
            float ar[4] = {a.x, a.y, a.z, a.w};
            float br[4] = {b.x, b.y, b.z, b.w};
            #pragma unroll
            for (int i = 0; i < 4; i++)
                #pragma unroll
                for (int j = 0; j < 4; j++)
                    acc[i][j] += ar[i] * br[j];
        }
    }

    #pragma unroll
    for (int i = 0; i < 4; i++) {
        int tok = m0 + ty * 4 + i;
        #pragma unroll
        for (int j = 0; j < 4; j++) {
            int col = n0 + tx * 4 + j;
            out[(size_t)tok * DMODEL + col] = acc[i][j] + bo[col];
        }
    }
}

// ---------------------------------------------------------------------------
extern "C" void kernel_launch(void* const* d_in, const int* in_sizes, int n_in,
                              void* d_out, int out_size)
{
    const float* x  = (const float*)d_in[0];
    const float* gm = (const float*)d_in[1];
    const float* Wq = (const float*)d_in[2];
    const float* Wk = (const float*)d_in[3];
    const float* Wv = (const float*)d_in[4];
    const float* Wo = (const float*)d_in[5];
    const float* bo = (const float*)d_in[6];
    float* out = (float*)d_out;

    mask_kernel<<<2, 192>>>(gm);
    plan_kernel<<<1, 256>>>();

    dim3 gq(DMODEL / 64, NTOK / 64, 3);
    qkv_gemm<<<gq, 256>>>(x, Wq, Wk, Wv);

    dim3 gg(128, 7, HEADS);
    gather_kernel<<<gg, 320>>>();

    meanv_kernel<<<HEADS, 320>>>();

    dim3 ga(MAXBLK, HEADS);
    attn_kernel<<<ga, 128>>>();

    fill_kernel<<<128, 256>>>();

    dim3 go(DMODEL / 64, NTOK / 64);
    out_gemm<<<go, 256>>>(Wo, bo, out);
}

// round 6
// speedup vs baseline: 2.5929x; 2.5929x over previous
#include <cuda_runtime.h>
#include <float.h>

#define NTOK   4096
#define DMODEL 320
#define HEADS  8
#define DH     40
#define NPHASE 3
#define KTILE  64
#define QBLK   64
#define MAXBLK 80
#define SPLIT  4

// ---------------- scratch (__device__ globals; no allocation allowed) -------
__device__ float g_q[HEADS * NTOK * DH];
__device__ float g_k[HEADS * NTOK * DH];
__device__ float g_v[HEADS * NTOK * DH];
__device__ float g_o[NTOK * DMODEL];
__device__ unsigned g_mb[NPHASE * (NTOK / 32)];

// planning data
__device__ int g_grp_cnt[8], g_grp_off[8];
__device__ int g_qidx[NTOK];
__device__ int g_kcnt[8];
__device__ int g_kidx[8][NTOK];
__device__ int g_bmap_sig[MAXBLK], g_bmap_qoff[MAXBLK], g_bmap_qend[MAXBLK];
__device__ int g_nblocks;

// compacted K/V: [sig-1][head][jc][40]
__device__ float g_kc[7 * HEADS * NTOK * DH];
__device__ float g_vc[7 * HEADS * NTOK * DH];
__device__ float g_meanv[HEADS * DH];

// split-K partials: indexed [split][head][ql]
__device__ float g_pacc[SPLIT * HEADS * NTOK * DH];
__device__ float g_pm[SPLIT * HEADS * NTOK];
__device__ float g_pl[SPLIT * HEADS * NTOK];

// ---------------------------------------------------------------------------
// Pack guidance mask into bitwords
// ---------------------------------------------------------------------------
__global__ void mask_kernel(const float* __restrict__ gm) {
    int w = blockIdx.x * blockDim.x + threadIdx.x;
    if (w < NPHASE * (NTOK / 32)) {
        unsigned bits = 0;
        #pragma unroll 8
        for (int b = 0; b < 32; b++)
            if (gm[w * 32 + b] != 0.0f) bits |= (1u << b);
        g_mb[w] = bits;
    }
}

// ---------------------------------------------------------------------------
// Plan kernel (deterministic scan-based grouping)
// ---------------------------------------------------------------------------
__global__ __launch_bounds__(256) void plan_kernel() {
    __shared__ int sq[8][256];
    __shared__ int sk[8][256];
    __shared__ int base_q[8];
    const int t = threadIdx.x;

    unsigned bits_arr[16];
    int cq[8], ck[8];
    #pragma unroll
    for (int s = 0; s < 8; s++) { cq[s] = 0; ck[s] = 0; }

    for (int u = 0; u < 16; u++) {
        int i = t * 16 + u;
        unsigned b = 0;
        #pragma unroll
        for (int p = 0; p < NPHASE; p++)
            b |= ((g_mb[p * 128 + (i >> 5)] >> (i & 31)) & 1u) << p;
        bits_arr[u] = b;
        cq[b]++;
        #pragma unroll
        for (int s = 1; s < 8; s++)
            if (b & (unsigned)s) ck[s]++;
    }
    #pragma unroll
    for (int s = 0; s < 8; s++) { sq[s][t] = cq[s]; sk[s][t] = ck[s]; }
    __syncthreads();

    for (int g = 0; g < 15; g++) {
        int* arr = (g < 8) ? sq[g] : sk[g - 7];
        for (int off = 1; off < 256; off <<= 1) {
            int u = (t >= off) ? arr[t - off] : 0;
            __syncthreads();
            arr[t] += u;
            __syncthreads();
        }
    }

    if (t == 0) {
        int acc = 0;
        for (int s = 0; s < 8; s++) {
            base_q[s] = acc;
            g_grp_off[s] = acc;
            int tot = sq[s][255];
            g_grp_cnt[s] = tot;
            acc += tot;
        }
        for (int s = 1; s < 8; s++) g_kcnt[s] = sk[s][255];
        int nb = 0;
        for (int s = 1; s < 8; s++) {
            int cnt = sq[s][255], off = base_q[s];
            for (int b = 0; b * QBLK < cnt; b++) {
                g_bmap_sig[nb] = s;
                g_bmap_qoff[nb] = off + b * QBLK;
                g_bmap_qend[nb] = off + cnt;
                nb++;
            }
        }
        g_nblocks = nb;
    }
    __syncthreads();

    int qcur[8], kcur[8];
    #pragma unroll
    for (int s = 0; s < 8; s++) {
        qcur[s] = base_q[s] + sq[s][t] - cq[s];
        kcur[s] = sk[s][t] - ck[s];
    }
    for (int u = 0; u < 16; u++) {
        int i = t * 16 + u;
        unsigned b = bits_arr[u];
        g_qidx[qcur[b]++] = i;
        #pragma unroll
        for (int s = 1; s < 8; s++)
            if (b & (unsigned)s) g_kidx[s][kcur[s]++] = i;
    }
}

// ---------------------------------------------------------------------------
// QKV projection
// ---------------------------------------------------------------------------
__global__ __launch_bounds__(256) void qkv_gemm(
    const float* __restrict__ X,
    const float* __restrict__ Wq, const float* __restrict__ Wk,
    const float* __restrict__ Wv)
{
    const float* W = (blockIdx.z == 0) ? Wq : (blockIdx.z == 1) ? Wk : Wv;
    float* Dst = (blockIdx.z == 0) ? g_q : (blockIdx.z == 1) ? g_k : g_v;

    __shared__ float As[16][64];
    __shared__ float Bs[16][64];

    const int tid = threadIdx.x;
    const int m0 = blockIdx.y * 64;
    const int n0 = blockIdx.x * 64;
    const int tx = tid % 16, ty = tid / 16;
    const int arow = tid / 4,  acol = (tid % 4) * 4;
    const int brow = tid / 16, bcol = (tid % 16) * 4;

    float acc[4][4];
    #pragma unroll
    for (int i = 0; i < 4; i++)
        #pragma unroll
        for (int j = 0; j < 4; j++) acc[i][j] = 0.0f;

    for (int k0 = 0; k0 < DMODEL; k0 += 16) {
        float4 av = *(const float4*)(X + (size_t)(m0 + arow) * DMODEL + k0 + acol);
        float4 bv = *(const float4*)(W + (size_t)(k0 + brow) * DMODEL + n0 + bcol);
        __syncthreads();
        As[acol + 0][arow] = av.x;
        As[acol + 1][arow] = av.y;
        As[acol + 2][arow] = av.z;
        As[acol + 3][arow] = av.w;
        *(float4*)&Bs[brow][bcol] = bv;
        __syncthreads();
        #pragma unroll
        for (int kk = 0; kk < 16; kk++) {
            float4 a = *(const float4*)&As[kk][ty * 4];
            float4 b = *(const float4*)&Bs[kk][tx * 4];
            float ar[4] = {a.x, a.y, a.z, a.w};
            float br[4] = {b.x, b.y, b.z, b.w};
            #pragma unroll
            for (int i = 0; i < 4; i++)
                #pragma unroll
                for (int j = 0; j < 4; j++)
                    acc[i][j] += ar[i] * br[j];
        }
    }

    #pragma unroll
    for (int i = 0; i < 4; i++) {
        int tok = m0 + ty * 4 + i;
        #pragma unroll
        for (int j = 0; j < 4; j++) {
            int hc = n0 + tx * 4 + j;
            int h = hc / DH, d = hc % DH;
            Dst[(size_t)h * NTOK * DH + (size_t)tok * DH + d] = acc[i][j];
        }
    }
}

// ---------------------------------------------------------------------------
// Gather compacted K/V; zero-pad to multiple of KTILE rows.
// ---------------------------------------------------------------------------
__global__ __launch_bounds__(320) void gather_kernel() {
    const int sig = blockIdx.y + 1;
    const int head = blockIdx.z;
    const int kc = g_kcnt[sig];
    const int pad = (kc + KTILE - 1) & ~(KTILE - 1);
    const int jc = blockIdx.x * 32 + threadIdx.x / 10;
    const int c4 = threadIdx.x % 10;
    if (jc >= pad) return;

    size_t dst = ((size_t)((sig - 1) * HEADS + head) * NTOK + jc) * DH + c4 * 4;
    float4 kv = make_float4(0.f, 0.f, 0.f, 0.f);
    float4 vv = make_float4(0.f, 0.f, 0.f, 0.f);
    if (jc < kc) {
        int j = g_kidx[sig][jc];
        size_t src = ((size_t)head * NTOK + j) * DH + c4 * 4;
        kv = *(const float4*)(g_k + src);
        vv = *(const float4*)(g_v + src);
    }
    *(float4*)(g_kc + dst) = kv;
    *(float4*)(g_vc + dst) = vv;
}

// ---------------------------------------------------------------------------
// Per-head V column mean (for fully-masked rows)
// ---------------------------------------------------------------------------
__global__ __launch_bounds__(320) void meanv_kernel() {
    __shared__ float red[320];
    const int head = blockIdx.x;
    const int t = threadIdx.x;
    const int d = t % DH, r = t / DH;
    float s = 0.0f;
    for (int j = r; j < NTOK; j += 8)
        s += g_v[((size_t)head * NTOK + j) * DH + d];
    red[t] = s;
    __syncthreads();
    if (r == 0) {
        float tot = 0.0f;
        #pragma unroll
        for (int rr = 0; rr < 8; rr++) tot += red[rr * DH + d];
        g_meanv[head * DH + d] = tot * (1.0f / (float)NTOK);
    }
}

// ---------------------------------------------------------------------------
// Fill g_o rows for signature-0 queries with meanV
// ---------------------------------------------------------------------------
__global__ __launch_bounds__(256) void fill_kernel() {
    __shared__ float mv[DMODEL];
    const int t = threadIdx.x;
    for (int i = t; i < DMODEL; i += 256) mv[i] = g_meanv[i];
    __syncthreads();
    const int cnt = g_grp_cnt[0], off = g_grp_off[0];
    const int ql = blockIdx.x * 32 + t / 8;
    if (ql >= cnt) return;
    const int qi = g_qidx[off + ql];
    const int c = t % 8;
    float4* dst = (float4*)(g_o + (size_t)qi * DMODEL);
    const float4* src = (const float4*)mv;
    #pragma unroll
    for (int k = c; k < DMODEL / 4; k += 8) dst[k] = src[k];
}

// ---------------------------------------------------------------------------
// Split-K flash attention over compacted keys. One thread per query.
// grid (MAXBLK, HEADS, SPLIT); each z-slice covers 1/SPLIT of the key tiles,
// writing unnormalized partials (acc, m, l).
// ---------------------------------------------------------------------------
__global__ __launch_bounds__(QBLK) void attn_kernel() {
    if (blockIdx.x >= g_nblocks) return;
    __shared__ __align__(16) float ksh[KTILE * DH];
    __shared__ __align__(16) float vsh[KTILE * DH];

    const int tid  = threadIdx.x;
    const int head = blockIdx.y;
    const int spl  = blockIdx.z;
    const int sig  = g_bmap_sig[blockIdx.x];
    const int qoff = g_bmap_qoff[blockIdx.x];
    const int qend = g_bmap_qend[blockIdx.x];
    const int ql   = qoff + tid;
    const bool vq  = ql < qend;
    const int qi   = g_qidx[vq ? ql : qoff];
    const int n_k  = g_kcnt[sig];
    const float scale = 0.15811388300841898f;  // 40^-0.5

    // this split's key range (tile-aligned)
    const int n_tiles = (n_k + KTILE - 1) / KTILE;
    const int tiles_per = (n_tiles + SPLIT - 1) / SPLIT;
    const int t_start = spl * tiles_per * KTILE;
    int t_end = (spl + 1) * tiles_per * KTILE;
    if (t_end > n_k) t_end = n_k;

    const float* Kb = g_kc + (size_t)((sig - 1) * HEADS + head) * NTOK * DH;
    const float* Vb = g_vc + (size_t)((sig - 1) * HEADS + head) * NTOK * DH;

    // pre-scaled q
    float4 q[10];
    {
        const float4* qp = (const float4*)(g_q + ((size_t)head * NTOK + qi) * DH);
        #pragma unroll
        for (int i = 0; i < 10; i++) {
            float4 v = qp[i];
            v.x *= scale; v.y *= scale; v.z *= scale; v.w *= scale;
            q[i] = v;
        }
    }

    float m = -FLT_MAX, l = 0.0f;
    float acc[DH];
    #pragma unroll
    for (int d = 0; d < DH; d++) acc[d] = 0.0f;

    for (int t0 = t_start; t0 < t_end; t0 += KTILE) {
        __syncthreads();
        const float4* kg = (const float4*)(Kb + (size_t)t0 * DH);
        const float4* vg = (const float4*)(Vb + (size_t)t0 * DH);
        float4* ks4 = (float4*)ksh;
        float4* vs4 = (float4*)vsh;
        #pragma unroll
        for (int i = tid; i < KTILE * DH / 4; i += QBLK) {
            ks4[i] = kg[i];   // zero-padded region guaranteed by gather
            vs4[i] = vg[i];
        }
        __syncthreads();

        const int lim = (t_end - t0 < KTILE) ? (t_end - t0) : KTILE;
        for (int c = 0; c < lim; c += 16) {
            float s[16];
            float cmax = -FLT_MAX;
            #pragma unroll
            for (int j = 0; j < 16; j++) {
                const float4* kr = (const float4*)(ksh + (c + j) * DH);
                float sv = 0.0f;
                #pragma unroll
                for (int d4 = 0; d4 < 10; d4++) {
                    float4 kv = kr[d4];
                    sv += q[d4].x * kv.x + q[d4].y * kv.y
                        + q[d4].z * kv.z + q[d4].w * kv.w;
                }
                s[j] = (c + j < lim) ? sv : -FLT_MAX;
                cmax = fmaxf(cmax, s[j]);
            }
            float mnew = fmaxf(m, cmax);
            float corr = __expf(m - mnew);
            l *= corr;
            #pragma unroll
            for (int d = 0; d < DH; d++) acc[d] *= corr;
            #pragma unroll
            for (int j = 0; j < 16; j++) {
                float pj = __expf(s[j] - mnew);
                l += pj;
                const float4* vr = (const float4*)(vsh + (c + j) * DH);
                #pragma unroll
                for (int d4 = 0; d4 < 10; d4++) {
                    float4 vv = vr[d4];
                    acc[d4 * 4 + 0] += pj * vv.x;
                    acc[d4 * 4 + 1] += pj * vv.y;
                    acc[d4 * 4 + 2] += pj * vv.z;
                    acc[d4 * 4 + 3] += pj * vv.w;
                }
            }
            m = mnew;
        }
    }

    if (vq) {
        size_t base = (size_t)(spl * HEADS + head) * NTOK + ql;
        g_pm[base] = m;
        g_pl[base] = l;
        float4* pp = (float4*)(g_pacc + base * DH);
        #pragma unroll
        for (int d4 = 0; d4 < 10; d4++) {
            float4 r;
            r.x = acc[d4 * 4 + 0];
            r.y = acc[d4 * 4 + 1];
            r.z = acc[d4 * 4 + 2];
            r.w = acc[d4 * 4 + 3];
            pp[d4] = r;
        }
    }
}

// ---------------------------------------------------------------------------
// Merge SPLIT partials per (query, head): log-sum-exp combine, normalize,
// scatter into g_o. One thread per (ql, head).
// ---------------------------------------------------------------------------
__global__ __launch_bounds__(256) void reduce_kernel() {
    const int nq0 = g_grp_cnt[0];
    const int total = (NTOK - nq0) * HEADS;
    const int idx = blockIdx.x * 256 + threadIdx.x;
    if (idx >= total) return;
    const int ql = nq0 + idx / HEADS;
    const int head = idx % HEADS;

    float ms[SPLIT], ls[SPLIT];
    float m = -FLT_MAX;
    #pragma unroll
    for (int s = 0; s < SPLIT; s++) {
        size_t base = (size_t)(s * HEADS + head) * NTOK + ql;
        ms[s] = g_pm[base];
        ls[s] = g_pl[base];
        m = fmaxf(m, ms[s]);
    }
    float w[SPLIT];
    float l = 0.0f;
    #pragma unroll
    for (int s = 0; s < SPLIT; s++) {
        w[s] = __expf(ms[s] - m);
        l += ls[s] * w[s];
    }
    const float inv = 1.0f / l;

    const int qi = g_qidx[ql];
    float* op = g_o + (size_t)qi * DMODEL + head * DH;
    #pragma unroll
    for (int d4 = 0; d4 < 10; d4++) {
        float4 sum = make_float4(0.f, 0.f, 0.f, 0.f);
        #pragma unroll
        for (int s = 0; s < SPLIT; s++) {
            size_t base = (size_t)(s * HEADS + head) * NTOK + ql;
            float4 a = *(const float4*)(g_pacc + base * DH + d4 * 4);
            sum.x += w[s] * a.x;
            sum.y += w[s] * a.y;
            sum.z += w[s] * a.z;
            sum.w += w[s] * a.w;
        }
        float4 r;
        r.x = sum.x * inv; r.y = sum.y * inv;
        r.z = sum.z * inv; r.w = sum.w * inv;
        *(float4*)(op + d4 * 4) = r;
    }
}

// ---------------------------------------------------------------------------
// Output projection: g_o(4096x320) @ Wo + bo -> d_out
// ---------------------------------------------------------------------------
__global__ __launch_bounds__(256) void out_gemm(
    const float* __restrict__ Wo, const float* __restrict__ bo,
    float* __restrict__ out)
{
    __shared__ float As[16][64];
    __shared__ float Bs[16][64];

    const int tid = threadIdx.x;
    const int m0 = blockIdx.y * 64;
    const int n0 = blockIdx.x * 64;
    const int tx = tid % 16, ty = tid / 16;
    const int arow = tid / 4,  acol = (tid % 4) * 4;
    const int brow = tid / 16, bcol = (tid % 16) * 4;

    float acc[4][4];
    #pragma unroll
    for (int i = 0; i < 4; i++)
        #pragma unroll
        for (int j = 0; j < 4; j++) acc[i][j] = 0.0f;

    for (int k0 = 0; k0 < DMODEL; k0 += 16) {
        float4 av = *(const float4*)(g_o + (size_t)(m0 + arow) * DMODEL + k0 + acol);
        float4 bv = *(const float4*)(Wo + (size_t)(k0 + brow) * DMODEL + n0 + bcol);
        __syncthreads();
        As[acol + 0][arow] = av.x;
        As[acol + 1][arow] = av.y;
        As[acol + 2][arow] = av.z;
        As[acol + 3][arow] = av.w;
        *(float4*)&Bs[brow][bcol] = bv;
        __syncthreads();
        #pragma unroll
        for (int kk = 0; kk < 16; kk++) {
            float4 a = *(const float4*)&As[kk][ty * 4];
            float4 b = *(const float4*)&Bs[kk][tx * 4];
            float ar[4] = {a.x, a.y, a.z, a.w};
            float br[4] = {b.x, b.y, b.z, b.w};
            #pragma unroll
            for (int i = 0; i < 4; i++)
                #pragma unroll
                for (int j = 0; j < 4; j++)
                    acc[i][j] += ar[i] * br[j];
        }
    }

    #pragma unroll
    for (int i = 0; i < 4; i++) {
        int tok = m0 + ty * 4 + i;
        #pragma unroll
        for (int j = 0; j < 4; j++) {
            int col = n0 + tx * 4 + j;
            out[(size_t)tok * DMODEL + col] = acc[i][j] + bo[col];
        }
    }
}

// ---------------------------------------------------------------------------
extern "C" void kernel_launch(void* const* d_in, const int* in_sizes, int n_in,
                              void* d_out, int out_size)
{
    const float* x  = (const float*)d_in[0];
    const float* gm = (const float*)d_in[1];
    const float* Wq = (const float*)d_in[2];
    const float* Wk = (const float*)d_in[3];
    const float* Wv = (const float*)d_in[4];
    const float* Wo = (const float*)d_in[5];
    const float* bo = (const float*)d_in[6];
    float* out = (float*)d_out;

    mask_kernel<<<2, 192>>>(gm);
    plan_kernel<<<1, 256>>>();

    dim3 gq(DMODEL / 64, NTOK / 64, 3);
    qkv_gemm<<<gq, 256>>>(x, Wq, Wk, Wv);

    dim3 gg(128, 7, HEADS);
    gather_kernel<<<gg, 320>>>();

    meanv_kernel<<<HEADS, 320>>>();

    dim3 ga(MAXBLK, HEADS, SPLIT);
    attn_kernel<<<ga, QBLK>>>();

    reduce_kernel<<<(NTOK * HEADS + 255) / 256, 256>>>();

    fill_kernel<<<128, 256>>>();

    dim3 go(DMODEL / 64, NTOK / 64);
    out_gemm<<<go, 256>>>(Wo, bo, out);
}

// round 7
// speedup vs baseline: 2.8159x; 1.0860x over previous
#include <cuda_runtime.h>
#include <float.h>

#define NTOK   4096
#define DMODEL 320
#define HEADS  8
#define DH     40
#define NPHASE 3
#define KTILE  64
#define QBLK   64
#define UT     4          // key tiles per uniform work unit (256 keys)
#define MAXU   1152       // >= (64+7)*16 worst-case units
#define MAXSPL 16

// ---------------- scratch (__device__ globals; no allocation allowed) -------
__device__ float g_q[HEADS * NTOK * DH];
__device__ float g_k[HEADS * NTOK * DH];
__device__ float g_v[HEADS * NTOK * DH];
__device__ float g_o[NTOK * DMODEL];
__device__ unsigned g_mb[NPHASE * (NTOK / 32)];

// planning data
__device__ int g_grp_cnt[8], g_grp_off[8];
__device__ int g_qidx[NTOK];
__device__ int g_kcnt[8];
__device__ int g_kidx[8][NTOK];
__device__ int g_nsplit[8];
__device__ int g_u_sig[MAXU], g_u_qoff[MAXU], g_u_qend[MAXU];
__device__ int g_u_t0[MAXU], g_u_t1[MAXU], g_u_spl[MAXU];
__device__ int g_nunits;

// compacted K/V: [sig-1][head][jc][40]
__device__ float g_kc[7 * HEADS * NTOK * DH];
__device__ float g_vc[7 * HEADS * NTOK * DH];
__device__ float g_meanv[HEADS * DH];

// split partials: indexed [spl][head][ql]
__device__ float g_pacc[MAXSPL * HEADS * NTOK * DH];
__device__ float g_pm[MAXSPL * HEADS * NTOK];
__device__ float g_pl[MAXSPL * HEADS * NTOK];

__device__ __forceinline__ float ex2(float x) {
    float r;
    asm("ex2.approx.ftz.f32 %0, %1;" : "=f"(r) : "f"(x));
    return r;
}

// ---------------------------------------------------------------------------
// Pack guidance mask into bitwords
// ---------------------------------------------------------------------------
__global__ void mask_kernel(const float* __restrict__ gm) {
    int w = blockIdx.x * blockDim.x + threadIdx.x;
    if (w < NPHASE * (NTOK / 32)) {
        unsigned bits = 0;
        #pragma unroll 8
        for (int b = 0; b < 32; b++)
            if (gm[w * 32 + b] != 0.0f) bits |= (1u << b);
        g_mb[w] = bits;
    }
}

// ---------------------------------------------------------------------------
// Plan kernel: group queries/keys by signature + build uniform work units
// ---------------------------------------------------------------------------
__global__ __launch_bounds__(256) void plan_kernel() {
    __shared__ int sq[8][256];
    __shared__ int sk[8][256];
    __shared__ int base_q[8];
    const int t = threadIdx.x;

    unsigned bits_arr[16];
    int cq[8], ck[8];
    #pragma unroll
    for (int s = 0; s < 8; s++) { cq[s] = 0; ck[s] = 0; }

    for (int u = 0; u < 16; u++) {
        int i = t * 16 + u;
        unsigned b = 0;
        #pragma unroll
        for (int p = 0; p < NPHASE; p++)
            b |= ((g_mb[p * 128 + (i >> 5)] >> (i & 31)) & 1u) << p;
        bits_arr[u] = b;
        cq[b]++;
        #pragma unroll
        for (int s = 1; s < 8; s++)
            if (b & (unsigned)s) ck[s]++;
    }
    #pragma unroll
    for (int s = 0; s < 8; s++) { sq[s][t] = cq[s]; sk[s][t] = ck[s]; }
    __syncthreads();

    for (int g = 0; g < 15; g++) {
        int* arr = (g < 8) ? sq[g] : sk[g - 7];
        for (int off = 1; off < 256; off <<= 1) {
            int u = (t >= off) ? arr[t - off] : 0;
            __syncthreads();
            arr[t] += u;
            __syncthreads();
        }
    }

    if (t == 0) {
        int acc = 0;
        for (int s = 0; s < 8; s++) {
            base_q[s] = acc;
            g_grp_off[s] = acc;
            int tot = sq[s][255];
            g_grp_cnt[s] = tot;
            acc += tot;
        }
        int nu = 0;
        for (int s = 1; s < 8; s++) {
            int kc = sk[s][255];
            g_kcnt[s] = kc;
            int cnt = sq[s][255], off = base_q[s];
            int tiles = (kc + KTILE - 1) / KTILE;
            int ns = (tiles + UT - 1) / UT;
            g_nsplit[s] = ns;
            for (int b = 0; b * QBLK < cnt; b++) {
                for (int sp = 0; sp < ns; sp++) {
                    g_u_sig[nu] = s;
                    g_u_qoff[nu] = off + b * QBLK;
                    g_u_qend[nu] = off + cnt;
                    g_u_t0[nu] = sp * UT * KTILE;
                    int t1 = (sp + 1) * UT * KTILE;
                    g_u_t1[nu] = (t1 < kc) ? t1 : kc;
                    g_u_spl[nu] = sp;
                    nu++;
                }
            }
        }
        g_nunits = nu;
    }
    __syncthreads();

    int qcur[8], kcur[8];
    #pragma unroll
    for (int s = 0; s < 8; s++) {
        qcur[s] = base_q[s] + sq[s][t] - cq[s];
        kcur[s] = sk[s][t] - ck[s];
    }
    for (int u = 0; u < 16; u++) {
        int i = t * 16 + u;
        unsigned b = bits_arr[u];
        g_qidx[qcur[b]++] = i;
        #pragma unroll
        for (int s = 1; s < 8; s++)
            if (b & (unsigned)s) g_kidx[s][kcur[s]++] = i;
    }
}

// ---------------------------------------------------------------------------
// QKV projection: X(4096x320) @ W(320x320) -> head-split [h][n][40]
// Tile 128x64, BK=16, 256 threads, 8x4 per thread.
// ---------------------------------------------------------------------------
__global__ __launch_bounds__(256) void qkv_gemm(
    const float* __restrict__ X,
    const float* __restrict__ Wq, const float* __restrict__ Wk,
    const float* __restrict__ Wv)
{
    const float* W = (blockIdx.z == 0) ? Wq : (blockIdx.z == 1) ? Wk : Wv;
    float* Dst = (blockIdx.z == 0) ? g_q : (blockIdx.z == 1) ? g_k : g_v;

    __shared__ float As[16][128];
    __shared__ float Bs[16][64];

    const int tid = threadIdx.x;
    const int m0 = blockIdx.y * 128;
    const int n0 = blockIdx.x * 64;
    const int tx = tid % 16, ty = tid / 16;
    const int ar = tid / 4,  ac = (tid % 4) * 4;    // A: rows ar, ar+64; cols ac..ac+3
    const int br = tid / 16, bc = (tid % 16) * 4;   // B: row br, cols bc..bc+3

    float acc[8][4];
    #pragma unroll
    for (int i = 0; i < 8; i++)
        #pragma unroll
        for (int j = 0; j < 4; j++) acc[i][j] = 0.0f;

    for (int k0 = 0; k0 < DMODEL; k0 += 16) {
        float4 a0 = *(const float4*)(X + (size_t)(m0 + ar) * DMODEL + k0 + ac);
        float4 a1 = *(const float4*)(X + (size_t)(m0 + ar + 64) * DMODEL + k0 + ac);
        float4 bv = *(const float4*)(W + (size_t)(k0 + br) * DMODEL + n0 + bc);
        __syncthreads();
        As[ac + 0][ar] = a0.x; As[ac + 1][ar] = a0.y;
        As[ac + 2][ar] = a0.z; As[ac + 3][ar] = a0.w;
        As[ac + 0][ar + 64] = a1.x; As[ac + 1][ar + 64] = a1.y;
        As[ac + 2][ar + 64] = a1.z; As[ac + 3][ar + 64] = a1.w;
        *(float4*)&Bs[br][bc] = bv;
        __syncthreads();
        #pragma unroll
        for (int kk = 0; kk < 16; kk++) {
            float4 av0 = *(const float4*)&As[kk][ty * 8];
            float4 av1 = *(const float4*)&As[kk][ty * 8 + 4];
            float4 b = *(const float4*)&Bs[kk][tx * 4];
            float a[8] = {av0.x, av0.y, av0.z, av0.w, av1.x, av1.y, av1.z, av1.w};
            float bb[4] = {b.x, b.y, b.z, b.w};
            #pragma unroll
            for (int i = 0; i < 8; i++)
                #pragma unroll
                for (int j = 0; j < 4; j++)
                    acc[i][j] += a[i] * bb[j];
        }
    }

    #pragma unroll
    for (int i = 0; i < 8; i++) {
        int tok = m0 + ty * 8 + i;
        #pragma unroll
        for (int j = 0; j < 4; j++) {
            int hc = n0 + tx * 4 + j;
            int h = hc / DH, d = hc % DH;
            Dst[(size_t)h * NTOK * DH + (size_t)tok * DH + d] = acc[i][j];
        }
    }
}

// ---------------------------------------------------------------------------
// Gather compacted K/V; zero-pad to multiple of KTILE rows.
// ---------------------------------------------------------------------------
__global__ __launch_bounds__(320) void gather_kernel() {
    const int sig = blockIdx.y + 1;
    const int head = blockIdx.z;
    const int kc = g_kcnt[sig];
    const int pad = (kc + KTILE - 1) & ~(KTILE - 1);
    const int jc = blockIdx.x * 32 + threadIdx.x / 10;
    const int c4 = threadIdx.x % 10;
    if (jc >= pad) return;

    size_t dst = ((size_t)((sig - 1) * HEADS + head) * NTOK + jc) * DH + c4 * 4;
    float4 kv = make_float4(0.f, 0.f, 0.f, 0.f);
    float4 vv = make_float4(0.f, 0.f, 0.f, 0.f);
    if (jc < kc) {
        int j = g_kidx[sig][jc];
        size_t src = ((size_t)head * NTOK + j) * DH + c4 * 4;
        kv = *(const float4*)(g_k + src);
        vv = *(const float4*)(g_v + src);
    }
    *(float4*)(g_kc + dst) = kv;
    *(float4*)(g_vc + dst) = vv;
}

// ---------------------------------------------------------------------------
// Per-head V column mean (for fully-masked rows)
// ---------------------------------------------------------------------------
__global__ __launch_bounds__(320) void meanv_kernel() {
    __shared__ float red[320];
    const int head = blockIdx.x;
    const int t = threadIdx.x;
    const int d = t % DH, r = t / DH;
    float s = 0.0f;
    for (int j = r; j < NTOK; j += 8)
        s += g_v[((size_t)head * NTOK + j) * DH + d];
    red[t] = s;
    __syncthreads();
    if (r == 0) {
        float tot = 0.0f;
        #pragma unroll
        for (int rr = 0; rr < 8; rr++) tot += red[rr * DH + d];
        g_meanv[head * DH + d] = tot * (1.0f / (float)NTOK);
    }
}

// ---------------------------------------------------------------------------
// Fill g_o rows for signature-0 queries with meanV
// ---------------------------------------------------------------------------
__global__ __launch_bounds__(256) void fill_kernel() {
    __shared__ float mv[DMODEL];
    const int t = threadIdx.x;
    for (int i = t; i < DMODEL; i += 256) mv[i] = g_meanv[i];
    __syncthreads();
    const int cnt = g_grp_cnt[0], off = g_grp_off[0];
    const int ql = blockIdx.x * 32 + t / 8;
    if (ql >= cnt) return;
    const int qi = g_qidx[off + ql];
    const int c = t % 8;
    float4* dst = (float4*)(g_o + (size_t)qi * DMODEL);
    const float4* src = (const float4*)mv;
    #pragma unroll
    for (int k = c; k < DMODEL / 4; k += 8) dst[k] = src[k];
}

// ---------------------------------------------------------------------------
// Flash attention over uniform work units. One thread per query.
// grid (MAXU, HEADS). Log2-domain softmax (scale pre-multiplied by log2 e).
// ---------------------------------------------------------------------------
__global__ __launch_bounds__(QBLK) void attn_kernel() {
    if (blockIdx.x >= g_nunits) return;
    __shared__ __align__(16) float ksh[KTILE * DH];
    __shared__ __align__(16) float vsh[KTILE * DH];

    const int tid  = threadIdx.x;
    const int head = blockIdx.y;
    const int uix  = blockIdx.x;
    const int sig  = g_u_sig[uix];
    const int qoff = g_u_qoff[uix];
    const int qend = g_u_qend[uix];
    const int t_start = g_u_t0[uix];
    const int t_end   = g_u_t1[uix];
    const int spl  = g_u_spl[uix];
    const int ql   = qoff + tid;
    const bool vq  = ql < qend;
    const int qi   = g_qidx[vq ? ql : qoff];
    // 40^-0.5 * log2(e): softmax computed in base-2 domain
    const float scale = 0.15811388300841898f * 1.4426950408889634f;

    const float* Kb = g_kc + (size_t)((sig - 1) * HEADS + head) * NTOK * DH;
    const float* Vb = g_vc + (size_t)((sig - 1) * HEADS + head) * NTOK * DH;

    float4 q[10];
    {
        const float4* qp = (const float4*)(g_q + ((size_t)head * NTOK + qi) * DH);
        #pragma unroll
        for (int i = 0; i < 10; i++) {
            float4 v = qp[i];
            v.x *= scale; v.y *= scale; v.z *= scale; v.w *= scale;
            q[i] = v;
        }
    }

    float m = -FLT_MAX, l = 0.0f;
    float acc[DH];
    #pragma unroll
    for (int d = 0; d < DH; d++) acc[d] = 0.0f;

    for (int t0 = t_start; t0 < t_end; t0 += KTILE) {
        __syncthreads();
        const float4* kg = (const float4*)(Kb + (size_t)t0 * DH);
        const float4* vg = (const float4*)(Vb + (size_t)t0 * DH);
        float4* ks4 = (float4*)ksh;
        float4* vs4 = (float4*)vsh;
        #pragma unroll
        for (int i = tid; i < KTILE * DH / 4; i += QBLK) {
            ks4[i] = kg[i];
            vs4[i] = vg[i];
        }
        __syncthreads();

        const int lim = (t_end - t0 < KTILE) ? (t_end - t0) : KTILE;
        for (int c = 0; c < lim; c += 16) {
            float s[16];
            float cmax = -FLT_MAX;
            #pragma unroll
            for (int j = 0; j < 16; j++) {
                const float4* kr = (const float4*)(ksh + (c + j) * DH);
                float sv = 0.0f;
                #pragma unroll
                for (int d4 = 0; d4 < 10; d4++) {
                    float4 kv = kr[d4];
                    sv += q[d4].x * kv.x + q[d4].y * kv.y
                        + q[d4].z * kv.z + q[d4].w * kv.w;
                }
                s[j] = (c + j < lim) ? sv : -FLT_MAX;
                cmax = fmaxf(cmax, s[j]);
            }
            float mnew = fmaxf(m, cmax);
            float corr = ex2(m - mnew);
            l *= corr;
            #pragma unroll
            for (int d = 0; d < DH; d++) acc[d] *= corr;
            #pragma unroll
            for (int j = 0; j < 16; j++) {
                float pj = ex2(s[j] - mnew);
                l += pj;
                const float4* vr = (const float4*)(vsh + (c + j) * DH);
                #pragma unroll
                for (int d4 = 0; d4 < 10; d4++) {
                    float4 vv = vr[d4];
                    acc[d4 * 4 + 0] += pj * vv.x;
                    acc[d4 * 4 + 1] += pj * vv.y;
                    acc[d4 * 4 + 2] += pj * vv.z;
                    acc[d4 * 4 + 3] += pj * vv.w;
                }
            }
            m = mnew;
        }
    }

    if (vq) {
        size_t base = (size_t)(spl * HEADS + head) * NTOK + ql;
        g_pm[base] = m;
        g_pl[base] = l;
        float4* pp = (float4*)(g_pacc + base * DH);
        #pragma unroll
        for (int d4 = 0; d4 < 10; d4++) {
            float4 r;
            r.x = acc[d4 * 4 + 0];
            r.y = acc[d4 * 4 + 1];
            r.z = acc[d4 * 4 + 2];
            r.w = acc[d4 * 4 + 3];
            pp[d4] = r;
        }
    }
}

// ---------------------------------------------------------------------------
// Merge variable split partials per (query, head) and scatter into g_o.
// ---------------------------------------------------------------------------
__global__ __launch_bounds__(256) void reduce_kernel() {
    const int nq0 = g_grp_cnt[0];
    const int total = (NTOK - nq0) * HEADS;
    const int idx = blockIdx.x * 256 + threadIdx.x;
    if (idx >= total) return;
    const int ql = nq0 + idx / HEADS;
    const int head = idx % HEADS;

    // find signature of this query (groups are contiguous)
    int sig = 1;
    #pragma unroll
    for (int s = 2; s < 8; s++)
        if (ql >= g_grp_off[s]) sig = s;
    const int ns = g_nsplit[sig];

    float m = -FLT_MAX;
    for (int s = 0; s < ns; s++) {
        float ms = g_pm[(size_t)(s * HEADS + head) * NTOK + ql];
        m = fmaxf(m, ms);
    }
    float l = 0.0f;
    for (int s = 0; s < ns; s++) {
        size_t base = (size_t)(s * HEADS + head) * NTOK + ql;
        l += g_pl[base] * ex2(g_pm[base] - m);
    }
    const float inv = 1.0f / l;

    const int qi = g_qidx[ql];
    float* op = g_o + (size_t)qi * DMODEL + head * DH;
    float sum[DH];
    #pragma unroll
    for (int d = 0; d < DH; d++) sum[d] = 0.0f;
    for (int s = 0; s < ns; s++) {
        size_t base = (size_t)(s * HEADS + head) * NTOK + ql;
        float w = ex2(g_pm[base] - m);
        const float4* pa = (const float4*)(g_pacc + base * DH);
        #pragma unroll
        for (int d4 = 0; d4 < 10; d4++) {
            float4 a = pa[d4];
            sum[d4 * 4 + 0] += w * a.x;
            sum[d4 * 4 + 1] += w * a.y;
            sum[d4 * 4 + 2] += w * a.z;
            sum[d4 * 4 + 3] += w * a.w;
        }
    }
    #pragma unroll
    for (int d4 = 0; d4 < 10; d4++) {
        float4 r;
        r.x = sum[d4 * 4 + 0] * inv;
        r.y = sum[d4 * 4 + 1] * inv;
        r.z = sum[d4 * 4 + 2] * inv;
        r.w = sum[d4 * 4 + 3] * inv;
        *(float4*)(op + d4 * 4) = r;
    }
}

// ---------------------------------------------------------------------------
// Output projection: g_o(4096x320) @ Wo + bo -> d_out. Tile 128x64, 8x4/thread.
// ---------------------------------------------------------------------------
__global__ __launch_bounds__(256) void out_gemm(
    const float* __restrict__ Wo, const float* __restrict__ bo,
    float* __restrict__ out)
{
    __shared__ float As[16][128];
    __shared__ float Bs[16][64];

    const int tid = threadIdx.x;
    const int m0 = blockIdx.y * 128;
    const int n0 = blockIdx.x * 64;
    const int tx = tid % 16, ty = tid / 16;
    const int ar = tid / 4,  ac = (tid % 4) * 4;
    const int br = tid / 16, bc = (tid % 16) * 4;

    float acc[8][4];
    #pragma unroll
    for (int i = 0; i < 8; i++)
        #pragma unroll
        for (int j = 0; j < 4; j++) acc[i][j] = 0.0f;

    for (int k0 = 0; k0 < DMODEL; k0 += 16) {
        float4 a0 = *(const float4*)(g_o + (size_t)(m0 + ar) * DMODEL + k0 + ac);
        float4 a1 = *(const float4*)(g_o + (size_t)(m0 + ar + 64) * DMODEL + k0 + ac);
        float4 bv = *(const float4*)(Wo + (size_t)(k0 + br) * DMODEL + n0 + bc);
        __syncthreads();
        As[ac + 0][ar] = a0.x; As[ac + 1][ar] = a0.y;
        As[ac + 2][ar] = a0.z; As[ac + 3][ar] = a0.w;
        As[ac + 0][ar + 64] = a1.x; As[ac + 1][ar + 64] = a1.y;
        As[ac + 2][ar + 64] = a1.z; As[ac + 3][ar + 64] = a1.w;
        *(float4*)&Bs[br][bc] = bv;
        __syncthreads();
        #pragma unroll
        for (int kk = 0; kk < 16; kk++) {
            float4 av0 = *(const float4*)&As[kk][ty * 8];
            float4 av1 = *(const float4*)&As[kk][ty * 8 + 4];
            float4 b = *(const float4*)&Bs[kk][tx * 4];
            float a[8] = {av0.x, av0.y, av0.z, av0.w, av1.x, av1.y, av1.z, av1.w};
            float bb[4] = {b.x, b.y, b.z, b.w};
            #pragma unroll
            for (int i = 0; i < 8; i++)
                #pragma unroll
                for (int j = 0; j < 4; j++)
                    acc[i][j] += a[i] * bb[j];
        }
    }

    float4 bias = *(const float4*)(bo + n0 + tx * 4);
    #pragma unroll
    for (int i = 0; i < 8; i++) {
        int tok = m0 + ty * 8 + i;
        float4 r;
        r.x = acc[i][0] + bias.x;
        r.y = acc[i][1] + bias.y;
        r.z = acc[i][2] + bias.z;
        r.w = acc[i][3] + bias.w;
        *(float4*)(out + (size_t)tok * DMODEL + n0 + tx * 4) = r;
    }
}

// ---------------------------------------------------------------------------
extern "C" void kernel_launch(void* const* d_in, const int* in_sizes, int n_in,
                              void* d_out, int out_size)
{
    const float* x  = (const float*)d_in[0];
    const float* gm = (const float*)d_in[1];
    const float* Wq = (const float*)d_in[2];
    const float* Wk = (const float*)d_in[3];
    const float* Wv = (const float*)d_in[4];
    const float* Wo = (const float*)d_in[5];
    const float* bo = (const float*)d_in[6];
    float* out = (float*)d_out;

    mask_kernel<<<2, 192>>>(gm);
    plan_kernel<<<1, 256>>>();

    dim3 gq(DMODEL / 64, NTOK / 128, 3);
    qkv_gemm<<<gq, 256>>>(x, Wq, Wk, Wv);

    dim3 gg(128, 7, HEADS);
    gather_kernel<<<gg, 320>>>();

    meanv_kernel<<<HEADS, 320>>>();

    dim3 ga(MAXU, HEADS);
    attn_kernel<<<ga, QBLK>>>();

    reduce_kernel<<<(NTOK * HEADS + 255) / 256, 256>>>();

    fill_kernel<<<128, 256>>>();

    dim3 go(DMODEL / 64, NTOK / 128);
    out_gemm<<<go, 256>>>(Wo, bo, out);
}

// round 8
// speedup vs baseline: 2.8907x; 1.0265x over previous
#include <cuda_runtime.h>
#include <float.h>

#define NTOK   4096
#define DMODEL 320
#define HEADS  8
#define DH     40
#define NPHASE 3
#define KTILE  64
#define QBLK   64
#define UT     4          // key tiles per uniform work unit (256 keys)
#define MAXU   1152
#define MAXSPL 16

typedef unsigned long long ull;

#define FMA2(d, a, b, c) \
    asm("fma.rn.f32x2 %0, %1, %2, %3;" : "=l"(d) : "l"(a), "l"(b), "l"(c))
#define MUL2(d, a, b) \
    asm("mul.rn.f32x2 %0, %1, %2;" : "=l"(d) : "l"(a), "l"(b))
#define PACK2(d, lo, hi) \
    asm("mov.b64 %0, {%1, %2};" : "=l"(d) : "f"(lo), "f"(hi))
#define UNPACK2(lo, hi, v) \
    asm("mov.b64 {%0, %1}, %2;" : "=f"(lo), "=f"(hi) : "l"(v))

// ---------------- scratch (__device__ globals; no allocation allowed) -------
__device__ float g_q[HEADS * NTOK * DH];
__device__ float g_k[HEADS * NTOK * DH];
__device__ float g_v[HEADS * NTOK * DH];
__device__ float g_o[NTOK * DMODEL];
__device__ unsigned g_mb[NPHASE * (NTOK / 32)];

// planning data
__device__ int g_grp_cnt[8], g_grp_off[8];
__device__ int g_qidx[NTOK];
__device__ int g_kcnt[8];
__device__ int g_kidx[8][NTOK];
__device__ int g_nsplit[8];
__device__ int g_u_sig[MAXU], g_u_qoff[MAXU], g_u_qend[MAXU];
__device__ int g_u_t0[MAXU], g_u_t1[MAXU], g_u_spl[MAXU];
__device__ int g_nunits;

// compacted K/V: [sig-1][head][jc][40]
__device__ float g_kc[7 * HEADS * NTOK * DH];
__device__ float g_vc[7 * HEADS * NTOK * DH];
__device__ float g_meanv[HEADS * DH];

// split partials: indexed [spl][head][ql]
__device__ float g_pacc[MAXSPL * HEADS * NTOK * DH];
__device__ float g_pm[MAXSPL * HEADS * NTOK];
__device__ float g_pl[MAXSPL * HEADS * NTOK];

__device__ __forceinline__ float ex2(float x) {
    float r;
    asm("ex2.approx.ftz.f32 %0, %1;" : "=f"(r) : "f"(x));
    return r;
}

// ---------------------------------------------------------------------------
// Pack guidance mask into bitwords
// ---------------------------------------------------------------------------
__global__ void mask_kernel(const float* __restrict__ gm) {
    int w = blockIdx.x * blockDim.x + threadIdx.x;
    if (w < NPHASE * (NTOK / 32)) {
        unsigned bits = 0;
        #pragma unroll 8
        for (int b = 0; b < 32; b++)
            if (gm[w * 32 + b] != 0.0f) bits |= (1u << b);
        g_mb[w] = bits;
    }
}

// ---------------------------------------------------------------------------
// Plan kernel: group queries/keys by signature + build uniform work units
// ---------------------------------------------------------------------------
__global__ __launch_bounds__(256) void plan_kernel() {
    __shared__ int sq[8][256];
    __shared__ int sk[8][256];
    __shared__ int base_q[8];
    const int t = threadIdx.x;

    unsigned bits_arr[16];
    int cq[8], ck[8];
    #pragma unroll
    for (int s = 0; s < 8; s++) { cq[s] = 0; ck[s] = 0; }

    for (int u = 0; u < 16; u++) {
        int i = t * 16 + u;
        unsigned b = 0;
        #pragma unroll
        for (int p = 0; p < NPHASE; p++)
            b |= ((g_mb[p * 128 + (i >> 5)] >> (i & 31)) & 1u) << p;
        bits_arr[u] = b;
        cq[b]++;
        #pragma unroll
        for (int s = 1; s < 8; s++)
            if (b & (unsigned)s) ck[s]++;
    }
    #pragma unroll
    for (int s = 0; s < 8; s++) { sq[s][t] = cq[s]; sk[s][t] = ck[s]; }
    __syncthreads();

    for (int g = 0; g < 15; g++) {
        int* arr = (g < 8) ? sq[g] : sk[g - 7];
        for (int off = 1; off < 256; off <<= 1) {
            int u = (t >= off) ? arr[t - off] : 0;
            __syncthreads();
            arr[t] += u;
            __syncthreads();
        }
    }

    if (t == 0) {
        int acc = 0;
        for (int s = 0; s < 8; s++) {
            base_q[s] = acc;
            g_grp_off[s] = acc;
            int tot = sq[s][255];
            g_grp_cnt[s] = tot;
            acc += tot;
        }
        int nu = 0;
        for (int s = 1; s < 8; s++) {
            int kc = sk[s][255];
            g_kcnt[s] = kc;
            int cnt = sq[s][255], off = base_q[s];
            int tiles = (kc + KTILE - 1) / KTILE;
            int ns = (tiles + UT - 1) / UT;
            g_nsplit[s] = ns;
            for (int b = 0; b * QBLK < cnt; b++) {
                for (int sp = 0; sp < ns; sp++) {
                    g_u_sig[nu] = s;
                    g_u_qoff[nu] = off + b * QBLK;
                    g_u_qend[nu] = off + cnt;
                    g_u_t0[nu] = sp * UT * KTILE;
                    int t1 = (sp + 1) * UT * KTILE;
                    g_u_t1[nu] = (t1 < kc) ? t1 : kc;
                    g_u_spl[nu] = sp;
                    nu++;
                }
            }
        }
        g_nunits = nu;
    }
    __syncthreads();

    int qcur[8], kcur[8];
    #pragma unroll
    for (int s = 0; s < 8; s++) {
        qcur[s] = base_q[s] + sq[s][t] - cq[s];
        kcur[s] = sk[s][t] - ck[s];
    }
    for (int u = 0; u < 16; u++) {
        int i = t * 16 + u;
        unsigned b = bits_arr[u];
        g_qidx[qcur[b]++] = i;
        #pragma unroll
        for (int s = 1; s < 8; s++)
            if (b & (unsigned)s) g_kidx[s][kcur[s]++] = i;
    }
}

// ---------------------------------------------------------------------------
// QKV projection: X(4096x320) @ W(320x320) -> head-split [h][n][40]
// Tile 128x64, BK=16, 256 threads, 8x4 per thread; f32x2 packed over row pairs.
// ---------------------------------------------------------------------------
__global__ __launch_bounds__(256) void qkv_gemm(
    const float* __restrict__ X,
    const float* __restrict__ Wq, const float* __restrict__ Wk,
    const float* __restrict__ Wv)
{
    const float* W = (blockIdx.z == 0) ? Wq : (blockIdx.z == 1) ? Wk : Wv;
    float* Dst = (blockIdx.z == 0) ? g_q : (blockIdx.z == 1) ? g_k : g_v;

    __shared__ float As[16][128];
    __shared__ float Bs[16][64];

    const int tid = threadIdx.x;
    const int m0 = blockIdx.y * 128;
    const int n0 = blockIdx.x * 64;
    const int tx = tid % 16, ty = tid / 16;
    const int ar = tid / 4,  ac = (tid % 4) * 4;
    const int br = tid / 16, bc = (tid % 16) * 4;

    // acc2[rp][j]: row-pair rp (rows 2rp,2rp+1), column j
    ull acc2[4][4];
    #pragma unroll
    for (int i = 0; i < 4; i++)
        #pragma unroll
        for (int j = 0; j < 4; j++) acc2[i][j] = 0ull;

    for (int k0 = 0; k0 < DMODEL; k0 += 16) {
        float4 a0 = *(const float4*)(X + (size_t)(m0 + ar) * DMODEL + k0 + ac);
        float4 a1 = *(const float4*)(X + (size_t)(m0 + ar + 64) * DMODEL + k0 + ac);
        float4 bv = *(const float4*)(W + (size_t)(k0 + br) * DMODEL + n0 + bc);
        __syncthreads();
        As[ac + 0][ar] = a0.x; As[ac + 1][ar] = a0.y;
        As[ac + 2][ar] = a0.z; As[ac + 3][ar] = a0.w;
        As[ac + 0][ar + 64] = a1.x; As[ac + 1][ar + 64] = a1.y;
        As[ac + 2][ar + 64] = a1.z; As[ac + 3][ar + 64] = a1.w;
        *(float4*)&Bs[br][bc] = bv;
        __syncthreads();
        #pragma unroll
        for (int kk = 0; kk < 16; kk++) {
            // a row-pairs: 8 contiguous floats = 4 ull pairs
            ulonglong2 ap0 = *(const ulonglong2*)&As[kk][ty * 8];
            ulonglong2 ap1 = *(const ulonglong2*)&As[kk][ty * 8 + 4];
            float4 b = *(const float4*)&Bs[kk][tx * 4];
            ull bb[4];
            PACK2(bb[0], b.x, b.x);
            PACK2(bb[1], b.y, b.y);
            PACK2(bb[2], b.z, b.z);
            PACK2(bb[3], b.w, b.w);
            ull ap[4] = {ap0.x, ap0.y, ap1.x, ap1.y};
            #pragma unroll
            for (int rp = 0; rp < 4; rp++)
                #pragma unroll
                for (int j = 0; j < 4; j++)
                    FMA2(acc2[rp][j], ap[rp], bb[j], acc2[rp][j]);
        }
    }

    #pragma unroll
    for (int rp = 0; rp < 4; rp++) {
        #pragma unroll
        for (int j = 0; j < 4; j++) {
            float lo, hi;
            UNPACK2(lo, hi, acc2[rp][j]);
            int hc = n0 + tx * 4 + j;
            int h = hc / DH, d = hc % DH;
            int tok = m0 + ty * 8 + rp * 2;
            Dst[(size_t)h * NTOK * DH + (size_t)tok * DH + d] = lo;
            Dst[(size_t)h * NTOK * DH + (size_t)(tok + 1) * DH + d] = hi;
        }
    }
}

// ---------------------------------------------------------------------------
// Gather compacted K/V; zero-pad to multiple of KTILE rows.
// ---------------------------------------------------------------------------
__global__ __launch_bounds__(320) void gather_kernel() {
    const int sig = blockIdx.y + 1;
    const int head = blockIdx.z;
    const int kc = g_kcnt[sig];
    const int pad = (kc + KTILE - 1) & ~(KTILE - 1);
    const int jc = blockIdx.x * 32 + threadIdx.x / 10;
    const int c4 = threadIdx.x % 10;
    if (jc >= pad) return;

    size_t dst = ((size_t)((sig - 1) * HEADS + head) * NTOK + jc) * DH + c4 * 4;
    float4 kv = make_float4(0.f, 0.f, 0.f, 0.f);
    float4 vv = make_float4(0.f, 0.f, 0.f, 0.f);
    if (jc < kc) {
        int j = g_kidx[sig][jc];
        size_t src = ((size_t)head * NTOK + j) * DH + c4 * 4;
        kv = *(const float4*)(g_k + src);
        vv = *(const float4*)(g_v + src);
    }
    *(float4*)(g_kc + dst) = kv;
    *(float4*)(g_vc + dst) = vv;
}

// ---------------------------------------------------------------------------
// Per-head V column mean (for fully-masked rows)
// ---------------------------------------------------------------------------
__global__ __launch_bounds__(320) void meanv_kernel() {
    __shared__ float red[320];
    const int head = blockIdx.x;
    const int t = threadIdx.x;
    const int d = t % DH, r = t / DH;
    float s = 0.0f;
    for (int j = r; j < NTOK; j += 8)
        s += g_v[((size_t)head * NTOK + j) * DH + d];
    red[t] = s;
    __syncthreads();
    if (r == 0) {
        float tot = 0.0f;
        #pragma unroll
        for (int rr = 0; rr < 8; rr++) tot += red[rr * DH + d];
        g_meanv[head * DH + d] = tot * (1.0f / (float)NTOK);
    }
}

// ---------------------------------------------------------------------------
// Fill g_o rows for signature-0 queries with meanV
// ---------------------------------------------------------------------------
__global__ __launch_bounds__(256) void fill_kernel() {
    __shared__ float mv[DMODEL];
    const int t = threadIdx.x;
    for (int i = t; i < DMODEL; i += 256) mv[i] = g_meanv[i];
    __syncthreads();
    const int cnt = g_grp_cnt[0], off = g_grp_off[0];
    const int ql = blockIdx.x * 32 + t / 8;
    if (ql >= cnt) return;
    const int qi = g_qidx[off + ql];
    const int c = t % 8;
    float4* dst = (float4*)(g_o + (size_t)qi * DMODEL);
    const float4* src = (const float4*)mv;
    #pragma unroll
    for (int k = c; k < DMODEL / 4; k += 8) dst[k] = src[k];
}

// ---------------------------------------------------------------------------
// Flash attention over uniform work units, f32x2-packed arithmetic.
// One thread per query. Log2-domain softmax.
// ---------------------------------------------------------------------------
__global__ __launch_bounds__(QBLK) void attn_kernel() {
    if (blockIdx.x >= g_nunits) return;
    __shared__ __align__(16) float ksh[KTILE * DH];
    __shared__ __align__(16) float vsh[KTILE * DH];

    const int tid  = threadIdx.x;
    const int head = blockIdx.y;
    const int uix  = blockIdx.x;
    const int sig  = g_u_sig[uix];
    const int qoff = g_u_qoff[uix];
    const int qend = g_u_qend[uix];
    const int t_start = g_u_t0[uix];
    const int t_end   = g_u_t1[uix];
    const int spl  = g_u_spl[uix];
    const int ql   = qoff + tid;
    const bool vq  = ql < qend;
    const int qi   = g_qidx[vq ? ql : qoff];
    const float scale = 0.15811388300841898f * 1.4426950408889634f;

    const float* Kb = g_kc + (size_t)((sig - 1) * HEADS + head) * NTOK * DH;
    const float* Vb = g_vc + (size_t)((sig - 1) * HEADS + head) * NTOK * DH;

    // q pre-scaled, packed over d-pairs: 20 ull
    ull q2[20];
    {
        const float4* qp = (const float4*)(g_q + ((size_t)head * NTOK + qi) * DH);
        #pragma unroll
        for (int i = 0; i < 10; i++) {
            float4 v = qp[i];
            PACK2(q2[2 * i + 0], v.x * scale, v.y * scale);
            PACK2(q2[2 * i + 1], v.z * scale, v.w * scale);
        }
    }

    float m = -FLT_MAX, l = 0.0f;
    ull acc2[20];
    #pragma unroll
    for (int d = 0; d < 20; d++) acc2[d] = 0ull;

    for (int t0 = t_start; t0 < t_end; t0 += KTILE) {
        __syncthreads();
        const float4* kg = (const float4*)(Kb + (size_t)t0 * DH);
        const float4* vg = (const float4*)(Vb + (size_t)t0 * DH);
        float4* ks4 = (float4*)ksh;
        float4* vs4 = (float4*)vsh;
        #pragma unroll
        for (int i = tid; i < KTILE * DH / 4; i += QBLK) {
            ks4[i] = kg[i];
            vs4[i] = vg[i];
        }
        __syncthreads();

        const int lim = (t_end - t0 < KTILE) ? (t_end - t0) : KTILE;
        for (int c = 0; c < lim; c += 16) {
            float s[16];
            float cmax = -FLT_MAX;
            #pragma unroll
            for (int j = 0; j < 16; j++) {
                const ulonglong2* kr = (const ulonglong2*)(ksh + (c + j) * DH);
                ull sva = 0ull, svb = 0ull;
                #pragma unroll
                for (int d4 = 0; d4 < 10; d4++) {
                    ulonglong2 kv = kr[d4];
                    FMA2(sva, q2[2 * d4 + 0], kv.x, sva);
                    FMA2(svb, q2[2 * d4 + 1], kv.y, svb);
                }
                float la, ha, lb, hb;
                UNPACK2(la, ha, sva);
                UNPACK2(lb, hb, svb);
                float sv = (la + ha) + (lb + hb);
                s[j] = (c + j < lim) ? sv : -FLT_MAX;
                cmax = fmaxf(cmax, s[j]);
            }
            float mnew = fmaxf(m, cmax);
            float corr = ex2(m - mnew);
            l *= corr;
            {
                ull corr2;
                PACK2(corr2, corr, corr);
                #pragma unroll
                for (int d = 0; d < 20; d++) MUL2(acc2[d], acc2[d], corr2);
            }
            #pragma unroll
            for (int j = 0; j < 16; j++) {
                float pj = ex2(s[j] - mnew);
                l += pj;
                ull pj2;
                PACK2(pj2, pj, pj);
                const ulonglong2* vr = (const ulonglong2*)(vsh + (c + j) * DH);
                #pragma unroll
                for (int d4 = 0; d4 < 10; d4++) {
                    ulonglong2 vv = vr[d4];
                    FMA2(acc2[2 * d4 + 0], pj2, vv.x, acc2[2 * d4 + 0]);
                    FMA2(acc2[2 * d4 + 1], pj2, vv.y, acc2[2 * d4 + 1]);
                }
            }
            m = mnew;
        }
    }

    if (vq) {
        size_t base = (size_t)(spl * HEADS + head) * NTOK + ql;
        g_pm[base] = m;
        g_pl[base] = l;
        float4* pp = (float4*)(g_pacc + base * DH);
        #pragma unroll
        for (int d4 = 0; d4 < 10; d4++) {
            float4 r;
            UNPACK2(r.x, r.y, acc2[2 * d4 + 0]);
            UNPACK2(r.z, r.w, acc2[2 * d4 + 1]);
            pp[d4] = r;
        }
    }
}

// ---------------------------------------------------------------------------
// Merge variable split partials per (query, head) and scatter into g_o.
// ---------------------------------------------------------------------------
__global__ __launch_bounds__(256) void reduce_kernel() {
    const int nq0 = g_grp_cnt[0];
    const int total = (NTOK - nq0) * HEADS;
    const int idx = blockIdx.x * 256 + threadIdx.x;
    if (idx >= total) return;
    const int ql = nq0 + idx / HEADS;
    const int head = idx % HEADS;

    int sig = 1;
    #pragma unroll
    for (int s = 2; s < 8; s++)
        if (ql >= g_grp_off[s]) sig = s;
    const int ns = g_nsplit[sig];

    float m = -FLT_MAX;
    for (int s = 0; s < ns; s++) {
        float ms = g_pm[(size_t)(s * HEADS + head) * NTOK + ql];
        m = fmaxf(m, ms);
    }
    float l = 0.0f;
    for (int s = 0; s < ns; s++) {
        size_t base = (size_t)(s * HEADS + head) * NTOK + ql;
        l += g_pl[base] * ex2(g_pm[base] - m);
    }
    const float inv = 1.0f / l;

    const int qi = g_qidx[ql];
    float* op = g_o + (size_t)qi * DMODEL + head * DH;
    float sum[DH];
    #pragma unroll
    for (int d = 0; d < DH; d++) sum[d] = 0.0f;
    for (int s = 0; s < ns; s++) {
        size_t base = (size_t)(s * HEADS + head) * NTOK + ql;
        float w = ex2(g_pm[base] - m);
        const float4* pa = (const float4*)(g_pacc + base * DH);
        #pragma unroll
        for (int d4 = 0; d4 < 10; d4++) {
            float4 a = pa[d4];
            sum[d4 * 4 + 0] += w * a.x;
            sum[d4 * 4 + 1] += w * a.y;
            sum[d4 * 4 + 2] += w * a.z;
            sum[d4 * 4 + 3] += w * a.w;
        }
    }
    #pragma unroll
    for (int d4 = 0; d4 < 10; d4++) {
        float4 r;
        r.x = sum[d4 * 4 + 0] * inv;
        r.y = sum[d4 * 4 + 1] * inv;
        r.z = sum[d4 * 4 + 2] * inv;
        r.w = sum[d4 * 4 + 3] * inv;
        *(float4*)(op + d4 * 4) = r;
    }
}

// ---------------------------------------------------------------------------
// Output projection: g_o(4096x320) @ Wo + bo -> d_out. 128x64, f32x2 packed.
// ---------------------------------------------------------------------------
__global__ __launch_bounds__(256) void out_gemm(
    const float* __restrict__ Wo, const float* __restrict__ bo,
    float* __restrict__ out)
{
    __shared__ float As[16][128];
    __shared__ float Bs[16][64];

    const int tid = threadIdx.x;
    const int m0 = blockIdx.y * 128;
    const int n0 = blockIdx.x * 64;
    const int tx = tid % 16, ty = tid / 16;
    const int ar = tid / 4,  ac = (tid % 4) * 4;
    const int br = tid / 16, bc = (tid % 16) * 4;

    ull acc2[4][4];
    #pragma unroll
    for (int i = 0; i < 4; i++)
        #pragma unroll
        for (int j = 0; j < 4; j++) acc2[i][j] = 0ull;

    for (int k0 = 0; k0 < DMODEL; k0 += 16) {
        float4 a0 = *(const float4*)(g_o + (size_t)(m0 + ar) * DMODEL + k0 + ac);
        float4 a1 = *(const float4*)(g_o + (size_t)(m0 + ar + 64) * DMODEL + k0 + ac);
        float4 bv = *(const float4*)(Wo + (size_t)(k0 + br) * DMODEL + n0 + bc);
        __syncthreads();
        As[ac + 0][ar] = a0.x; As[ac + 1][ar] = a0.y;
        As[ac + 2][ar] = a0.z; As[ac + 3][ar] = a0.w;
        As[ac + 0][ar + 64] = a1.x; As[ac + 1][ar + 64] = a1.y;
        As[ac + 2][ar + 64] = a1.z; As[ac + 3][ar + 64] = a1.w;
        *(float4*)&Bs[br][bc] = bv;
        __syncthreads();
        #pragma unroll
        for (int kk = 0; kk < 16; kk++) {
            ulonglong2 ap0 = *(const ulonglong2*)&As[kk][ty * 8];
            ulonglong2 ap1 = *(const ulonglong2*)&As[kk][ty * 8 + 4];
            float4 b = *(const float4*)&Bs[kk][tx * 4];
            ull bb[4];
            PACK2(bb[0], b.x, b.x);
            PACK2(bb[1], b.y, b.y);
            PACK2(bb[2], b.z, b.z);
            PACK2(bb[3], b.w, b.w);
            ull ap[4] = {ap0.x, ap0.y, ap1.x, ap1.y};
            #pragma unroll
            for (int rp = 0; rp < 4; rp++)
                #pragma unroll
                for (int j = 0; j < 4; j++)
                    FMA2(acc2[rp][j], ap[rp], bb[j], acc2[rp][j]);
        }
    }

    float4 bias = *(const float4*)(bo + n0 + tx * 4);
    float bias_a[4] = {bias.x, bias.y, bias.z, bias.w};
    #pragma unroll
    for (int rp = 0; rp < 4; rp++) {
        int tok = m0 + ty * 8 + rp * 2;
        float4 r0, r1;
        float lo, hi;
        UNPACK2(lo, hi, acc2[rp][0]); r0.x = lo + bias_a[0]; r1.x = hi + bias_a[0];
        UNPACK2(lo, hi, acc2[rp][1]); r0.y = lo + bias_a[1]; r1.y = hi + bias_a[1];
        UNPACK2(lo, hi, acc2[rp][2]); r0.z = lo + bias_a[2]; r1.z = hi + bias_a[2];
        UNPACK2(lo, hi, acc2[rp][3]); r0.w = lo + bias_a[3]; r1.w = hi + bias_a[3];
        *(float4*)(out + (size_t)tok * DMODEL + n0 + tx * 4) = r0;
        *(float4*)(out + (size_t)(tok + 1) * DMODEL + n0 + tx * 4) = r1;
    }
}

// ---------------------------------------------------------------------------
extern "C" void kernel_launch(void* const* d_in, const int* in_sizes, int n_in,
                              void* d_out, int out_size)
{
    const float* x  = (const float*)d_in[0];
    const float* gm = (const float*)d_in[1];
    const float* Wq = (const float*)d_in[2];
    const float* Wk = (const float*)d_in[3];
    const float* Wv = (const float*)d_in[4];
    const float* Wo = (const float*)d_in[5];
    const float* bo = (const float*)d_in[6];
    float* out = (float*)d_out;

    mask_kernel<<<2, 192>>>(gm);
    plan_kernel<<<1, 256>>>();

    dim3 gq(DMODEL / 64, NTOK / 128, 3);
    qkv_gemm<<<gq, 256>>>(x, Wq, Wk, Wv);

    dim3 gg(128, 7, HEADS);
    gather_kernel<<<gg, 320>>>();

    meanv_kernel<<<HEADS, 320>>>();

    dim3 ga(MAXU, HEADS);
    attn_kernel<<<ga, QBLK>>>();

    reduce_kernel<<<(NTOK * HEADS + 255) / 256, 256>>>();

    fill_kernel<<<128, 256>>>();

    dim3 go(DMODEL / 64, NTOK / 128);
    out_gemm<<<go, 256>>>(Wo, bo, out);
}

// round 9
// speedup vs baseline: 2.9068x; 1.0056x over previous
#include <cuda_runtime.h>
#include <float.h>

#define NTOK   4096
#define DMODEL 320
#define HEADS  8
#define DH     40
#define NPHASE 3
#define KTILE  64
#define QBLK   64
#define UT     4          // key tiles per uniform work unit (256 keys)
#define MAXU   1152
#define MAXSPL 16

typedef unsigned long long ull;

#define FMA2(d, a, b, c) \
    asm("fma.rn.f32x2 %0, %1, %2, %3;" : "=l"(d) : "l"(a), "l"(b), "l"(c))
#define MUL2(d, a, b) \
    asm("mul.rn.f32x2 %0, %1, %2;" : "=l"(d) : "l"(a), "l"(b))
#define PACK2(d, lo, hi) \
    asm("mov.b64 %0, {%1, %2};" : "=l"(d) : "f"(lo), "f"(hi))
#define UNPACK2(lo, hi, v) \
    asm("mov.b64 {%0, %1}, %2;" : "=f"(lo), "=f"(hi) : "l"(v))

// ---------------- scratch (__device__ globals; no allocation allowed) -------
__device__ float g_q[HEADS * NTOK * DH];
__device__ float g_k[HEADS * NTOK * DH];
__device__ float g_v[HEADS * NTOK * DH];
__device__ float g_o[NTOK * DMODEL];
__device__ unsigned g_mb[NPHASE * (NTOK / 32)];

// planning data
__device__ int g_grp_cnt[8], g_grp_off[8];
__device__ int g_qidx[NTOK];
__device__ int g_kcnt[8];
__device__ int g_kidx[8][NTOK];
__device__ int g_nsplit[8];
__device__ int g_u_sig[MAXU], g_u_qoff[MAXU], g_u_qend[MAXU];
__device__ int g_u_t0[MAXU], g_u_t1[MAXU], g_u_spl[MAXU];
__device__ int g_nunits;

// compacted K/V: [sig-1][head][jc][40]
__device__ float g_kc[7 * HEADS * NTOK * DH];
__device__ float g_vc[7 * HEADS * NTOK * DH];
__device__ float g_meanv[HEADS * DH];

// split partials: indexed [spl][head][ql]
__device__ float g_pacc[MAXSPL * HEADS * NTOK * DH];
__device__ float g_pm[MAXSPL * HEADS * NTOK];
__device__ float g_pl[MAXSPL * HEADS * NTOK];

__device__ __forceinline__ float ex2(float x) {
    float r;
    asm("ex2.approx.ftz.f32 %0, %1;" : "=f"(r) : "f"(x));
    return r;
}

// ---------------------------------------------------------------------------
// Pack guidance mask into bitwords
// ---------------------------------------------------------------------------
__global__ void mask_kernel(const float* __restrict__ gm) {
    int w = blockIdx.x * blockDim.x + threadIdx.x;
    if (w < NPHASE * (NTOK / 32)) {
        unsigned bits = 0;
        #pragma unroll 8
        for (int b = 0; b < 32; b++)
            if (gm[w * 32 + b] != 0.0f) bits |= (1u << b);
        g_mb[w] = bits;
    }
}

// ---------------------------------------------------------------------------
// Plan kernel: group queries/keys by signature + build uniform work units
// ---------------------------------------------------------------------------
__global__ __launch_bounds__(256) void plan_kernel() {
    __shared__ int sq[8][256];
    __shared__ int sk[8][256];
    __shared__ int base_q[8];
    const int t = threadIdx.x;

    unsigned bits_arr[16];
    int cq[8], ck[8];
    #pragma unroll
    for (int s = 0; s < 8; s++) { cq[s] = 0; ck[s] = 0; }

    for (int u = 0; u < 16; u++) {
        int i = t * 16 + u;
        unsigned b = 0;
        #pragma unroll
        for (int p = 0; p < NPHASE; p++)
            b |= ((g_mb[p * 128 + (i >> 5)] >> (i & 31)) & 1u) << p;
        bits_arr[u] = b;
        cq[b]++;
        #pragma unroll
        for (int s = 1; s < 8; s++)
            if (b & (unsigned)s) ck[s]++;
    }
    #pragma unroll
    for (int s = 0; s < 8; s++) { sq[s][t] = cq[s]; sk[s][t] = ck[s]; }
    __syncthreads();

    for (int g = 0; g < 15; g++) {
        int* arr = (g < 8) ? sq[g] : sk[g - 7];
        for (int off = 1; off < 256; off <<= 1) {
            int u = (t >= off) ? arr[t - off] : 0;
            __syncthreads();
            arr[t] += u;
            __syncthreads();
        }
    }

    if (t == 0) {
        int acc = 0;
        for (int s = 0; s < 8; s++) {
            base_q[s] = acc;
            g_grp_off[s] = acc;
            int tot = sq[s][255];
            g_grp_cnt[s] = tot;
            acc += tot;
        }
        int nu = 0;
        for (int s = 1; s < 8; s++) {
            int kc = sk[s][255];
            g_kcnt[s] = kc;
            int cnt = sq[s][255], off = base_q[s];
            int tiles = (kc + KTILE - 1) / KTILE;
            int ns = (tiles + UT - 1) / UT;
            g_nsplit[s] = ns;
            for (int b = 0; b * QBLK < cnt; b++) {
                for (int sp = 0; sp < ns; sp++) {
                    g_u_sig[nu] = s;
                    g_u_qoff[nu] = off + b * QBLK;
                    g_u_qend[nu] = off + cnt;
                    g_u_t0[nu] = sp * UT * KTILE;
                    int t1 = (sp + 1) * UT * KTILE;
                    g_u_t1[nu] = (t1 < kc) ? t1 : kc;
                    g_u_spl[nu] = sp;
                    nu++;
                }
            }
        }
        g_nunits = nu;
    }
    __syncthreads();

    int qcur[8], kcur[8];
    #pragma unroll
    for (int s = 0; s < 8; s++) {
        qcur[s] = base_q[s] + sq[s][t] - cq[s];
        kcur[s] = sk[s][t] - ck[s];
    }
    for (int u = 0; u < 16; u++) {
        int i = t * 16 + u;
        unsigned b = bits_arr[u];
        g_qidx[qcur[b]++] = i;
        #pragma unroll
        for (int s = 1; s < 8; s++)
            if (b & (unsigned)s) g_kidx[s][kcur[s]++] = i;
    }
}

// ---------------------------------------------------------------------------
// QKV projection: X(4096x320) @ W(320x320) -> head-split [h][n][40]
// Tile 128x64, BK=16, 256 threads, 8x4 per thread; f32x2 packed over row pairs.
// ---------------------------------------------------------------------------
__global__ __launch_bounds__(256) void qkv_gemm(
    const float* __restrict__ X,
    const float* __restrict__ Wq, const float* __restrict__ Wk,
    const float* __restrict__ Wv)
{
    const float* W = (blockIdx.z == 0) ? Wq : (blockIdx.z == 1) ? Wk : Wv;
    float* Dst = (blockIdx.z == 0) ? g_q : (blockIdx.z == 1) ? g_k : g_v;

    __shared__ float As[16][128];
    __shared__ float Bs[16][64];

    const int tid = threadIdx.x;
    const int m0 = blockIdx.y * 128;
    const int n0 = blockIdx.x * 64;
    const int tx = tid % 16, ty = tid / 16;
    const int ar = tid / 4,  ac = (tid % 4) * 4;
    const int br = tid / 16, bc = (tid % 16) * 4;

    ull acc2[4][4];
    #pragma unroll
    for (int i = 0; i < 4; i++)
        #pragma unroll
        for (int j = 0; j < 4; j++) acc2[i][j] = 0ull;

    for (int k0 = 0; k0 < DMODEL; k0 += 16) {
        float4 a0 = *(const float4*)(X + (size_t)(m0 + ar) * DMODEL + k0 + ac);
        float4 a1 = *(const float4*)(X + (size_t)(m0 + ar + 64) * DMODEL + k0 + ac);
        float4 bv = *(const float4*)(W + (size_t)(k0 + br) * DMODEL + n0 + bc);
        __syncthreads();
        As[ac + 0][ar] = a0.x; As[ac + 1][ar] = a0.y;
        As[ac + 2][ar] = a0.z; As[ac + 3][ar] = a0.w;
        As[ac + 0][ar + 64] = a1.x; As[ac + 1][ar + 64] = a1.y;
        As[ac + 2][ar + 64] = a1.z; As[ac + 3][ar + 64] = a1.w;
        *(float4*)&Bs[br][bc] = bv;
        __syncthreads();
        #pragma unroll
        for (int kk = 0; kk < 16; kk++) {
            ulonglong2 ap0 = *(const ulonglong2*)&As[kk][ty * 8];
            ulonglong2 ap1 = *(const ulonglong2*)&As[kk][ty * 8 + 4];
            float4 b = *(const float4*)&Bs[kk][tx * 4];
            ull bb[4];
            PACK2(bb[0], b.x, b.x);
            PACK2(bb[1], b.y, b.y);
            PACK2(bb[2], b.z, b.z);
            PACK2(bb[3], b.w, b.w);
            ull ap[4] = {ap0.x, ap0.y, ap1.x, ap1.y};
            #pragma unroll
            for (int rp = 0; rp < 4; rp++)
                #pragma unroll
                for (int j = 0; j < 4; j++)
                    FMA2(acc2[rp][j], ap[rp], bb[j], acc2[rp][j]);
        }
    }

    #pragma unroll
    for (int rp = 0; rp < 4; rp++) {
        #pragma unroll
        for (int j = 0; j < 4; j++) {
            float lo, hi;
            UNPACK2(lo, hi, acc2[rp][j]);
            int hc = n0 + tx * 4 + j;
            int h = hc / DH, d = hc % DH;
            int tok = m0 + ty * 8 + rp * 2;
            Dst[(size_t)h * NTOK * DH + (size_t)tok * DH + d] = lo;
            Dst[(size_t)h * NTOK * DH + (size_t)(tok + 1) * DH + d] = hi;
        }
    }
}

// ---------------------------------------------------------------------------
// Gather compacted K/V; zero-pad to multiple of KTILE rows.
// ---------------------------------------------------------------------------
__global__ __launch_bounds__(320) void gather_kernel() {
    const int sig = blockIdx.y + 1;
    const int head = blockIdx.z;
    const int kc = g_kcnt[sig];
    const int pad = (kc + KTILE - 1) & ~(KTILE - 1);
    const int jc = blockIdx.x * 32 + threadIdx.x / 10;
    const int c4 = threadIdx.x % 10;
    if (jc >= pad) return;

    size_t dst = ((size_t)((sig - 1) * HEADS + head) * NTOK + jc) * DH + c4 * 4;
    float4 kv = make_float4(0.f, 0.f, 0.f, 0.f);
    float4 vv = make_float4(0.f, 0.f, 0.f, 0.f);
    if (jc < kc) {
        int j = g_kidx[sig][jc];
        size_t src = ((size_t)head * NTOK + j) * DH + c4 * 4;
        kv = *(const float4*)(g_k + src);
        vv = *(const float4*)(g_v + src);
    }
    *(float4*)(g_kc + dst) = kv;
    *(float4*)(g_vc + dst) = vv;
}

// ---------------------------------------------------------------------------
// Per-head V column mean (for fully-masked rows)
// ---------------------------------------------------------------------------
__global__ __launch_bounds__(320) void meanv_kernel() {
    __shared__ float red[320];
    const int head = blockIdx.x;
    const int t = threadIdx.x;
    const int d = t % DH, r = t / DH;
    float s = 0.0f;
    for (int j = r; j < NTOK; j += 8)
        s += g_v[((size_t)head * NTOK + j) * DH + d];
    red[t] = s;
    __syncthreads();
    if (r == 0) {
        float tot = 0.0f;
        #pragma unroll
        for (int rr = 0; rr < 8; rr++) tot += red[rr * DH + d];
        g_meanv[head * DH + d] = tot * (1.0f / (float)NTOK);
    }
}

// ---------------------------------------------------------------------------
// Fill g_o rows for signature-0 queries with meanV
// ---------------------------------------------------------------------------
__global__ __launch_bounds__(256) void fill_kernel() {
    __shared__ float mv[DMODEL];
    const int t = threadIdx.x;
    for (int i = t; i < DMODEL; i += 256) mv[i] = g_meanv[i];
    __syncthreads();
    const int cnt = g_grp_cnt[0], off = g_grp_off[0];
    const int ql = blockIdx.x * 32 + t / 8;
    if (ql >= cnt) return;
    const int qi = g_qidx[off + ql];
    const int c = t % 8;
    float4* dst = (float4*)(g_o + (size_t)qi * DMODEL);
    const float4* src = (const float4*)mv;
    #pragma unroll
    for (int k = c; k < DMODEL / 4; k += 8) dst[k] = src[k];
}

// ---------------------------------------------------------------------------
// Flash attention over uniform work units.
// 128 threads = 64 queries x 2 dim-halves. Each thread handles 20 dims of
// its query; score halves combined via shfl_xor(1). f32x2-packed math,
// log2-domain softmax. Doubles warps/SMSP and halves dependency chains
// vs the one-thread-per-query version.
// ---------------------------------------------------------------------------
__global__ __launch_bounds__(128) void attn_kernel() {
    if (blockIdx.x >= g_nunits) return;
    __shared__ __align__(16) float ksh[KTILE * DH];
    __shared__ __align__(16) float vsh[KTILE * DH];

    const int tid  = threadIdx.x;
    const int head = blockIdx.y;
    const int uix  = blockIdx.x;
    const int sig  = g_u_sig[uix];
    const int qoff = g_u_qoff[uix];
    const int qend = g_u_qend[uix];
    const int t_start = g_u_t0[uix];
    const int t_end   = g_u_t1[uix];
    const int spl  = g_u_spl[uix];
    const int q    = tid >> 1;          // query slot 0..63
    const int half = tid & 1;           // dim half: 0 -> dims 0..19, 1 -> 20..39
    const int ql   = qoff + q;
    const bool vq  = ql < qend;
    const int qi   = g_qidx[vq ? ql : qoff];
    const float scale = 0.15811388300841898f * 1.4426950408889634f;

    const float* Kb = g_kc + (size_t)((sig - 1) * HEADS + head) * NTOK * DH;
    const float* Vb = g_vc + (size_t)((sig - 1) * HEADS + head) * NTOK * DH;

    // this thread's 20-dim half of q, pre-scaled, packed: 10 ull
    ull q2[10];
    {
        const float4* qp = (const float4*)(g_q + ((size_t)head * NTOK + qi) * DH + half * 20);
        #pragma unroll
        for (int i = 0; i < 5; i++) {
            float4 v = qp[i];
            PACK2(q2[2 * i + 0], v.x * scale, v.y * scale);
            PACK2(q2[2 * i + 1], v.z * scale, v.w * scale);
        }
    }

    float m = -FLT_MAX, l = 0.0f;
    ull acc2[10];
    #pragma unroll
    for (int d = 0; d < 10; d++) acc2[d] = 0ull;

    for (int t0 = t_start; t0 < t_end; t0 += KTILE) {
        __syncthreads();
        const float4* kg = (const float4*)(Kb + (size_t)t0 * DH);
        const float4* vg = (const float4*)(Vb + (size_t)t0 * DH);
        float4* ks4 = (float4*)ksh;
        float4* vs4 = (float4*)vsh;
        #pragma unroll
        for (int i = tid; i < KTILE * DH / 4; i += 128) {
            ks4[i] = kg[i];
            vs4[i] = vg[i];
        }
        __syncthreads();

        const int lim = (t_end - t0 < KTILE) ? (t_end - t0) : KTILE;
        for (int c = 0; c < lim; c += 16) {
            float s[16];
            float cmax = -FLT_MAX;
            #pragma unroll
            for (int j = 0; j < 16; j++) {
                const ulonglong2* kr =
                    (const ulonglong2*)(ksh + (c + j) * DH + half * 20);
                ull sva = 0ull, svb = 0ull;
                // 20 dims = 5 ulonglong2 = 10 packed pairs
                ulonglong2 k0 = kr[0], k1 = kr[1], k2 = kr[2], k3 = kr[3], k4 = kr[4];
                FMA2(sva, q2[0], k0.x, sva);
                FMA2(svb, q2[1], k0.y, svb);
                FMA2(sva, q2[2], k1.x, sva);
                FMA2(svb, q2[3], k1.y, svb);
                FMA2(sva, q2[4], k2.x, sva);
                FMA2(svb, q2[5], k2.y, svb);
                FMA2(sva, q2[6], k3.x, sva);
                FMA2(svb, q2[7], k3.y, svb);
                FMA2(sva, q2[8], k4.x, sva);
                FMA2(svb, q2[9], k4.y, svb);
                float la, ha, lb, hb;
                UNPACK2(la, ha, sva);
                UNPACK2(lb, hb, svb);
                float svf = (la + ha) + (lb + hb);
                // combine the two dim-halves (partner = adjacent lane)
                svf += __shfl_xor_sync(0xffffffffu, svf, 1);
                s[j] = (c + j < lim) ? svf : -FLT_MAX;
                cmax = fmaxf(cmax, s[j]);
            }
            float mnew = fmaxf(m, cmax);
            float corr = ex2(m - mnew);
            l *= corr;
            {
                ull corr2;
                PACK2(corr2, corr, corr);
                #pragma unroll
                for (int d = 0; d < 10; d++) MUL2(acc2[d], acc2[d], corr2);
            }
            #pragma unroll
            for (int j = 0; j < 16; j++) {
                float pj = ex2(s[j] - mnew);
                l += pj;
                ull pj2;
                PACK2(pj2, pj, pj);
                const ulonglong2* vr =
                    (const ulonglong2*)(vsh + (c + j) * DH + half * 20);
                ulonglong2 v0 = vr[0], v1 = vr[1], v2 = vr[2], v3 = vr[3], v4 = vr[4];
                FMA2(acc2[0], pj2, v0.x, acc2[0]);
                FMA2(acc2[1], pj2, v0.y, acc2[1]);
                FMA2(acc2[2], pj2, v1.x, acc2[2]);
                FMA2(acc2[3], pj2, v1.y, acc2[3]);
                FMA2(acc2[4], pj2, v2.x, acc2[4]);
                FMA2(acc2[5], pj2, v2.y, acc2[5]);
                FMA2(acc2[6], pj2, v3.x, acc2[6]);
                FMA2(acc2[7], pj2, v3.y, acc2[7]);
                FMA2(acc2[8], pj2, v4.x, acc2[8]);
                FMA2(acc2[9], pj2, v4.y, acc2[9]);
            }
            m = mnew;
        }
    }

    if (vq) {
        size_t base = (size_t)(spl * HEADS + head) * NTOK + ql;
        if (half == 0) {
            g_pm[base] = m;
            g_pl[base] = l;
        }
        // each half writes its 20 floats (5 float4) of the partial accumulator
        float4* pp = (float4*)(g_pacc + base * DH + half * 20);
        #pragma unroll
        for (int d4 = 0; d4 < 5; d4++) {
            float4 r;
            UNPACK2(r.x, r.y, acc2[2 * d4 + 0]);
            UNPACK2(r.z, r.w, acc2[2 * d4 + 1]);
            pp[d4] = r;
        }
    }
}

// ---------------------------------------------------------------------------
// Merge variable split partials per (query, head) and scatter into g_o.
// ---------------------------------------------------------------------------
__global__ __launch_bounds__(256) void reduce_kernel() {
    const int nq0 = g_grp_cnt[0];
    const int total = (NTOK - nq0) * HEADS;
    const int idx = blockIdx.x * 256 + threadIdx.x;
    if (idx >= total) return;
    const int ql = nq0 + idx / HEADS;
    const int head = idx % HEADS;

    int sig = 1;
    #pragma unroll
    for (int s = 2; s < 8; s++)
        if (ql >= g_grp_off[s]) sig = s;
    const int ns = g_nsplit[sig];

    float m = -FLT_MAX;
    for (int s = 0; s < ns; s++) {
        float ms = g_pm[(size_t)(s * HEADS + head) * NTOK + ql];
        m = fmaxf(m, ms);
    }
    float l = 0.0f;
    for (int s = 0; s < ns; s++) {
        size_t base = (size_t)(s * HEADS + head) * NTOK + ql;
        l += g_pl[base] * ex2(g_pm[base] - m);
    }
    const float inv = 1.0f / l;

    const int qi = g_qidx[ql];
    float* op = g_o + (size_t)qi * DMODEL + head * DH;
    float sum[DH];
    #pragma unroll
    for (int d = 0; d < DH; d++) sum[d] = 0.0f;
    for (int s = 0; s < ns; s++) {
        size_t base = (size_t)(s * HEADS + head) * NTOK + ql;
        float w = ex2(g_pm[base] - m);
        const float4* pa = (const float4*)(g_pacc + base * DH);
        #pragma unroll
        for (int d4 = 0; d4 < 10; d4++) {
            float4 a = pa[d4];
            sum[d4 * 4 + 0] += w * a.x;
            sum[d4 * 4 + 1] += w * a.y;
            sum[d4 * 4 + 2] += w * a.z;
            sum[d4 * 4 + 3] += w * a.w;
        }
    }
    #pragma unroll
    for (int d4 = 0; d4 < 10; d4++) {
        float4 r;
        r.x = sum[d4 * 4 + 0] * inv;
        r.y = sum[d4 * 4 + 1] * inv;
        r.z = sum[d4 * 4 + 2] * inv;
        r.w = sum[d4 * 4 + 3] * inv;
        *(float4*)(op + d4 * 4) = r;
    }
}

// ---------------------------------------------------------------------------
// Output projection: g_o(4096x320) @ Wo + bo -> d_out. 128x64, f32x2 packed.
// ---------------------------------------------------------------------------
__global__ __launch_bounds__(256) void out_gemm(
    const float* __restrict__ Wo, const float* __restrict__ bo,
    float* __restrict__ out)
{
    __shared__ float As[16][128];
    __shared__ float Bs[16][64];

    const int tid = threadIdx.x;
    const int m0 = blockIdx.y * 128;
    const int n0 = blockIdx.x * 64;
    const int tx = tid % 16, ty = tid / 16;
    const int ar = tid / 4,  ac = (tid % 4) * 4;
    const int br = tid / 16, bc = (tid % 16) * 4;

    ull acc2[4][4];
    #pragma unroll
    for (int i = 0; i < 4; i++)
        #pragma unroll
        for (int j = 0; j < 4; j++) acc2[i][j] = 0ull;

    for (int k0 = 0; k0 < DMODEL; k0 += 16) {
        float4 a0 = *(const float4*)(g_o + (size_t)(m0 + ar) * DMODEL + k0 + ac);
        float4 a1 = *(const float4*)(g_o + (size_t)(m0 + ar + 64) * DMODEL + k0 + ac);
        float4 bv = *(const float4*)(Wo + (size_t)(k0 + br) * DMODEL + n0 + bc);
        __syncthreads();
        As[ac + 0][ar] = a0.x; As[ac + 1][ar] = a0.y;
        As[ac + 2][ar] = a0.z; As[ac + 3][ar] = a0.w;
        As[ac + 0][ar + 64] = a1.x; As[ac + 1][ar + 64] = a1.y;
        As[ac + 2][ar + 64] = a1.z; As[ac + 3][ar + 64] = a1.w;
        *(float4*)&Bs[br][bc] = bv;
        __syncthreads();
        #pragma unroll
        for (int kk = 0; kk < 16; kk++) {
            ulonglong2 ap0 = *(const ulonglong2*)&As[kk][ty * 8];
            ulonglong2 ap1 = *(const ulonglong2*)&As[kk][ty * 8 + 4];
            float4 b = *(const float4*)&Bs[kk][tx * 4];
            ull bb[4];
            PACK2(bb[0], b.x, b.x);
            PACK2(bb[1], b.y, b.y);
            PACK2(bb[2], b.z, b.z);
            PACK2(bb[3], b.w, b.w);
            ull ap[4] = {ap0.x, ap0.y, ap1.x, ap1.y};
            #pragma unroll
            for (int rp = 0; rp < 4; rp++)
                #pragma unroll
                for (int j = 0; j < 4; j++)
                    FMA2(acc2[rp][j], ap[rp], bb[j], acc2[rp][j]);
        }
    }

    float4 bias = *(const float4*)(bo + n0 + tx * 4);
    float bias_a[4] = {bias.x, bias.y, bias.z, bias.w};
    #pragma unroll
    for (int rp = 0; rp < 4; rp++) {
        int tok = m0 + ty * 8 + rp * 2;
        float4 r0, r1;
        float lo, hi;
        UNPACK2(lo, hi, acc2[rp][0]); r0.x = lo + bias_a[0]; r1.x = hi + bias_a[0];
        UNPACK2(lo, hi, acc2[rp][1]); r0.y = lo + bias_a[1]; r1.y = hi + bias_a[1];
        UNPACK2(lo, hi, acc2[rp][2]); r0.z = lo + bias_a[2]; r1.z = hi + bias_a[2];
        UNPACK2(lo, hi, acc2[rp][3]); r0.w = lo + bias_a[3]; r1.w = hi + bias_a[3];
        *(float4*)(out + (size_t)tok * DMODEL + n0 + tx * 4) = r0;
        *(float4*)(out + (size_t)(tok + 1) * DMODEL + n0 + tx * 4) = r1;
    }
}

// ---------------------------------------------------------------------------
extern "C" void kernel_launch(void* const* d_in, const int* in_sizes, int n_in,
                              void* d_out, int out_size)
{
    const float* x  = (const float*)d_in[0];
    const float* gm = (const float*)d_in[1];
    const float* Wq = (const float*)d_in[2];
    const float* Wk = (const float*)d_in[3];
    const float* Wv = (const float*)d_in[4];
    const float* Wo = (const float*)d_in[5];
    const float* bo = (const float*)d_in[6];
    float* out = (float*)d_out;

    mask_kernel<<<2, 192>>>(gm);
    plan_kernel<<<1, 256>>>();

    dim3 gq(DMODEL / 64, NTOK / 128, 3);
    qkv_gemm<<<gq, 256>>>(x, Wq, Wk, Wv);

    dim3 gg(128, 7, HEADS);
    gather_kernel<<<gg, 320>>>();

    meanv_kernel<<<HEADS, 320>>>();

    dim3 ga(MAXU, HEADS);
    attn_kernel<<<ga, 128>>>();

    reduce_kernel<<<(NTOK * HEADS + 255) / 256, 256>>>();

    fill_kernel<<<128, 256>>>();

    dim3 go(DMODEL / 64, NTOK / 128);
    out_gemm<<<go, 256>>>(Wo, bo, out);
}

// round 10
// speedup vs baseline: 3.1147x; 1.0715x over previous
#include <cuda_runtime.h>
#include <cuda_bf16.h>
#include <float.h>

#define NTOK   4096
#define DMODEL 320
#define HEADS  8
#define DH     40
#define NPHASE 3
#define KTILE  64
#define QBLK   64
#define UT     4
#define MAXU   1152
#define MAXSPL 16

typedef unsigned long long ull;

#define FMA2(d, a, b, c) \
    asm("fma.rn.f32x2 %0, %1, %2, %3;" : "=l"(d) : "l"(a), "l"(b), "l"(c))
#define MUL2(d, a, b) \
    asm("mul.rn.f32x2 %0, %1, %2;" : "=l"(d) : "l"(a), "l"(b))
#define PACK2(d, lo, hi) \
    asm("mov.b64 %0, {%1, %2};" : "=l"(d) : "f"(lo), "f"(hi))
#define UNPACK2(lo, hi, v) \
    asm("mov.b64 {%0, %1}, %2;" : "=f"(lo), "=f"(hi) : "l"(v))

#define LDSM_X4(r0, r1, r2, r3, addr) \
    asm volatile("ldmatrix.sync.aligned.m8n8.x4.shared.b16 {%0,%1,%2,%3}, [%4];" \
        : "=r"(r0), "=r"(r1), "=r"(r2), "=r"(r3) : "r"(addr))
#define LDSM_X4T(r0, r1, r2, r3, addr) \
    asm volatile("ldmatrix.sync.aligned.m8n8.x4.trans.shared.b16 {%0,%1,%2,%3}, [%4];" \
        : "=r"(r0), "=r"(r1), "=r"(r2), "=r"(r3) : "r"(addr))
#define MMA_BF16(c, a, b) \
    asm volatile("mma.sync.aligned.m16n8k16.row.col.f32.bf16.bf16.f32 " \
        "{%0,%1,%2,%3}, {%4,%5,%6,%7}, {%8,%9}, {%0,%1,%2,%3};" \
        : "+f"((c)[0]), "+f"((c)[1]), "+f"((c)[2]), "+f"((c)[3]) \
        : "r"((a)[0]), "r"((a)[1]), "r"((a)[2]), "r"((a)[3]), \
          "r"((b)[0]), "r"((b)[1]))

// ---------------- scratch (__device__ globals; no allocation allowed) -------
__device__ float g_q[HEADS * NTOK * DH];
__device__ float g_k[HEADS * NTOK * DH];
__device__ float g_v[HEADS * NTOK * DH];
__device__ float g_o[NTOK * DMODEL];

// planning data
__device__ int g_grp_cnt[8], g_grp_off[8];
__device__ int g_qidx[NTOK];
__device__ int g_kcnt[8];
__device__ int g_kidx[8][NTOK];
__device__ int g_nsplit[8];
__device__ int g_u_sig[MAXU], g_u_qoff[MAXU], g_u_qend[MAXU];
__device__ int g_u_t0[MAXU], g_u_t1[MAXU], g_u_spl[MAXU];
__device__ int g_nunits;

// compacted K/V: [sig-1][head][jc][40]
__device__ float g_kc[7 * HEADS * NTOK * DH];
__device__ float g_vc[7 * HEADS * NTOK * DH];
__device__ float g_meanv[HEADS * DH];

// split partials: indexed [spl][head][ql]
__device__ float g_pacc[MAXSPL * HEADS * NTOK * DH];
__device__ float g_pm[MAXSPL * HEADS * NTOK];
__device__ float g_pl[MAXSPL * HEADS * NTOK];

__device__ __forceinline__ float ex2(float x) {
    float r;
    asm("ex2.approx.ftz.f32 %0, %1;" : "=f"(r) : "f"(x));
    return r;
}
__device__ __forceinline__ unsigned s2u(const void* p) {
    return (unsigned)__cvta_generic_to_shared(p);
}

// ---------------------------------------------------------------------------
// Plan kernel (mask packing fused in; bitwords live in shared).
// ---------------------------------------------------------------------------
__global__ __launch_bounds__(256) void plan_kernel(const float* __restrict__ gm) {
    __shared__ unsigned smb[NPHASE * (NTOK / 32)];   // 384 words
    __shared__ int sq[8][256];
    __shared__ int sk[8][256];
    __shared__ int base_q[8];
    const int t = threadIdx.x;

    // pack guidance mask bits
    {
        unsigned bits = 0;
        #pragma unroll 8
        for (int b = 0; b < 32; b++)
            if (gm[t * 32 + b] != 0.0f) bits |= (1u << b);
        smb[t] = bits;
        if (t < 128) {
            unsigned bits2 = 0;
            #pragma unroll 8
            for (int b = 0; b < 32; b++)
                if (gm[(256 + t) * 32 + b] != 0.0f) bits2 |= (1u << b);
            smb[256 + t] = bits2;
        }
    }
    __syncthreads();

    unsigned bits_arr[16];
    int cq[8], ck[8];
    #pragma unroll
    for (int s = 0; s < 8; s++) { cq[s] = 0; ck[s] = 0; }

    for (int u = 0; u < 16; u++) {
        int i = t * 16 + u;
        unsigned b = 0;
        #pragma unroll
        for (int p = 0; p < NPHASE; p++)
            b |= ((smb[p * 128 + (i >> 5)] >> (i & 31)) & 1u) << p;
        bits_arr[u] = b;
        cq[b]++;
        #pragma unroll
        for (int s = 1; s < 8; s++)
            if (b & (unsigned)s) ck[s]++;
    }
    #pragma unroll
    for (int s = 0; s < 8; s++) { sq[s][t] = cq[s]; sk[s][t] = ck[s]; }
    __syncthreads();

    for (int g = 0; g < 15; g++) {
        int* arr = (g < 8) ? sq[g] : sk[g - 7];
        for (int off = 1; off < 256; off <<= 1) {
            int u = (t >= off) ? arr[t - off] : 0;
            __syncthreads();
            arr[t] += u;
            __syncthreads();
        }
    }

    if (t == 0) {
        int acc = 0;
        for (int s = 0; s < 8; s++) {
            base_q[s] = acc;
            g_grp_off[s] = acc;
            int tot = sq[s][255];
            g_grp_cnt[s] = tot;
            acc += tot;
        }
        int nu = 0;
        for (int s = 1; s < 8; s++) {
            int kc = sk[s][255];
            g_kcnt[s] = kc;
            int cnt = sq[s][255], off = base_q[s];
            int tiles = (kc + KTILE - 1) / KTILE;
            int ns = (tiles + UT - 1) / UT;
            g_nsplit[s] = ns;
            for (int b = 0; b * QBLK < cnt; b++) {
                for (int sp = 0; sp < ns; sp++) {
                    g_u_sig[nu] = s;
                    g_u_qoff[nu] = off + b * QBLK;
                    g_u_qend[nu] = off + cnt;
                    g_u_t0[nu] = sp * UT * KTILE;
                    int t1 = (sp + 1) * UT * KTILE;
                    g_u_t1[nu] = (t1 < kc) ? t1 : kc;
                    g_u_spl[nu] = sp;
                    nu++;
                }
            }
        }
        g_nunits = nu;
    }
    __syncthreads();

    int qcur[8], kcur[8];
    #pragma unroll
    for (int s = 0; s < 8; s++) {
        qcur[s] = base_q[s] + sq[s][t] - cq[s];
        kcur[s] = sk[s][t] - ck[s];
    }
    for (int u = 0; u < 16; u++) {
        int i = t * 16 + u;
        unsigned b = bits_arr[u];
        g_qidx[qcur[b]++] = i;
        #pragma unroll
        for (int s = 1; s < 8; s++)
            if (b & (unsigned)s) g_kidx[s][kcur[s]++] = i;
    }
}

// ---------------------------------------------------------------------------
// QKV projection via bf16 split-precision tensor-core MMA.
// C = Xh*Wh + Xh*Wl + Xl*Wh  (fp32 accum), rel err ~2^-16.
// Tile 128x64, BK=32, 256 threads = 8 warps (4M x 2N), warp tile 32x32.
// ---------------------------------------------------------------------------
#define SKA 40   // A smem row stride (bf16): 32 + 8 pad
#define SNB 72   // B smem row stride (bf16): 64 + 8 pad

__global__ __launch_bounds__(256) void qkv_gemm(
    const float* __restrict__ X,
    const float* __restrict__ Wq, const float* __restrict__ Wk,
    const float* __restrict__ Wv)
{
    const float* W = (blockIdx.z == 0) ? Wq : (blockIdx.z == 1) ? Wk : Wv;
    float* Dst = (blockIdx.z == 0) ? g_q : (blockIdx.z == 1) ? g_k : g_v;

    __shared__ __nv_bfloat16 Ah[128 * SKA], Al[128 * SKA];
    __shared__ __nv_bfloat16 Bh[32 * SNB],  Bl[32 * SNB];

    const int tid  = threadIdx.x;
    const int lane = tid & 31;
    const int wid  = tid >> 5;
    const int warp_m = wid >> 1;      // 0..3
    const int warp_n = wid & 1;       // 0..1
    const int m0 = blockIdx.y * 128;
    const int n0 = blockIdx.x * 64;

    const int quad = lane >> 3, rr = lane & 7;

    float c[2][4][4];
    #pragma unroll
    for (int mf = 0; mf < 2; mf++)
        #pragma unroll
        for (int nf = 0; nf < 4; nf++)
            #pragma unroll
            for (int r = 0; r < 4; r++) c[mf][nf][r] = 0.0f;

    // loader roles
    const int arow = tid >> 1, ahalf = (tid & 1) * 16;   // A: 128 rows x 2 halves
    const int brow = tid >> 3, bcol = (tid & 7) * 8;     // B: 32 rows x 8 col-chunks

    // ldmatrix lane base addresses (k-offset added per step)
    unsigned aAh[2], aAl[2];
    #pragma unroll
    for (int mf = 0; mf < 2; mf++) {
        int mrow = warp_m * 32 + mf * 16 + (quad & 1) * 8 + rr;
        int kcol = (quad >> 1) * 8;
        aAh[mf] = s2u(&Ah[mrow * SKA + kcol]);
        aAl[mf] = s2u(&Al[mrow * SKA + kcol]);
    }
    unsigned aBh[2], aBl[2];
    #pragma unroll
    for (int nf2 = 0; nf2 < 2; nf2++) {
        int krow = (quad & 1) * 8 + rr;
        int ncol = warp_n * 32 + nf2 * 16 + (quad >> 1) * 8;
        aBh[nf2] = s2u(&Bh[krow * SNB + ncol]);
        aBl[nf2] = s2u(&Bl[krow * SNB + ncol]);
    }

    for (int k0 = 0; k0 < DMODEL; k0 += 32) {
        // ---- load + split-convert into smem ----
        float4 av[4], wv[2];
        const float4* asrc = (const float4*)(X + (size_t)(m0 + arow) * DMODEL + k0 + ahalf);
        #pragma unroll
        for (int j = 0; j < 4; j++) av[j] = asrc[j];
        const float4* wsrc = (const float4*)(W + (size_t)(k0 + brow) * DMODEL + n0 + bcol);
        #pragma unroll
        for (int j = 0; j < 2; j++) wv[j] = wsrc[j];
        __syncthreads();   // previous iteration's ldmatrix reads complete

        #pragma unroll
        for (int j = 0; j < 4; j++) {
            float f[4] = {av[j].x, av[j].y, av[j].z, av[j].w};
            #pragma unroll
            for (int e = 0; e < 4; e += 2) {
                __nv_bfloat16 h0 = __float2bfloat16_rn(f[e]);
                __nv_bfloat16 h1 = __float2bfloat16_rn(f[e + 1]);
                __nv_bfloat16 l0 = __float2bfloat16_rn(f[e] - __bfloat162float(h0));
                __nv_bfloat16 l1 = __float2bfloat16_rn(f[e + 1] - __bfloat162float(h1));
                int off = arow * SKA + ahalf + j * 4 + e;
                *(__nv_bfloat162*)&Ah[off] = __nv_bfloat162(h0, h1);
                *(__nv_bfloat162*)&Al[off] = __nv_bfloat162(l0, l1);
            }
        }
        #pragma unroll
        for (int j = 0; j < 2; j++) {
            float f[4] = {wv[j].x, wv[j].y, wv[j].z, wv[j].w};
            #pragma unroll
            for (int e = 0; e < 4; e += 2) {
                __nv_bfloat16 h0 = __float2bfloat16_rn(f[e]);
                __nv_bfloat16 h1 = __float2bfloat16_rn(f[e + 1]);
                __nv_bfloat16 l0 = __float2bfloat16_rn(f[e] - __bfloat162float(h0));
                __nv_bfloat16 l1 = __float2bfloat16_rn(f[e + 1] - __bfloat162float(h1));
                int off = brow * SNB + bcol + j * 4 + e;
                *(__nv_bfloat162*)&Bh[off] = __nv_bfloat162(h0, h1);
                *(__nv_bfloat162*)&Bl[off] = __nv_bfloat162(l0, l1);
            }
        }
        __syncthreads();

        // ---- 2 x k16 MMA steps ----
        #pragma unroll
        for (int ks = 0; ks < 2; ks++) {
            const unsigned koffA = ks * 16 * 2;              // bytes
            const unsigned koffB = (unsigned)(ks * 16 * SNB * 2);
            unsigned ah[2][4], al[2][4];
            #pragma unroll
            for (int mf = 0; mf < 2; mf++) {
                LDSM_X4(ah[mf][0], ah[mf][1], ah[mf][2], ah[mf][3], aAh[mf] + koffA);
                LDSM_X4(al[mf][0], al[mf][1], al[mf][2], al[mf][3], aAl[mf] + koffA);
            }
            unsigned bh[4][2], bl[4][2];
            #pragma unroll
            for (int nf2 = 0; nf2 < 2; nf2++) {
                unsigned r0, r1, r2, r3;
                LDSM_X4T(r0, r1, r2, r3, aBh[nf2] + koffB);
                bh[nf2 * 2][0] = r0;  bh[nf2 * 2][1] = r1;
                bh[nf2 * 2 + 1][0] = r2;  bh[nf2 * 2 + 1][1] = r3;
                LDSM_X4T(r0, r1, r2, r3, aBl[nf2] + koffB);
                bl[nf2 * 2][0] = r0;  bl[nf2 * 2][1] = r1;
                bl[nf2 * 2 + 1][0] = r2;  bl[nf2 * 2 + 1][1] = r3;
            }
            #pragma unroll
            for (int mf = 0; mf < 2; mf++)
                #pragma unroll
                for (int nf = 0; nf < 4; nf++) {
                    MMA_BF16(c[mf][nf], ah[mf], bh[nf]);
                    MMA_BF16(c[mf][nf], ah[mf], bl[nf]);
                    MMA_BF16(c[mf][nf], al[mf], bh[nf]);
                }
        }
    }

    // ---- epilogue: head-split scatter (pairs never cross head boundary) ----
    #pragma unroll
    for (int mf = 0; mf < 2; mf++) {
        #pragma unroll
        for (int nf = 0; nf < 4; nf++) {
            int row = m0 + warp_m * 32 + mf * 16 + (lane >> 2);
            int col = n0 + warp_n * 32 + nf * 8 + (lane & 3) * 2;
            int h = col / DH, d = col % DH;
            float* base = Dst + (size_t)h * NTOK * DH;
            *(float2*)&base[(size_t)row * DH + d] =
                make_float2(c[mf][nf][0], c[mf][nf][1]);
            *(float2*)&base[(size_t)(row + 8) * DH + d] =
                make_float2(c[mf][nf][2], c[mf][nf][3]);
        }
    }
}

// ---------------------------------------------------------------------------
// Gather compacted K/V; zero-pad to multiple of KTILE rows.
// ---------------------------------------------------------------------------
__global__ __launch_bounds__(320) void gather_kernel() {
    const int sig = blockIdx.y + 1;
    const int head = blockIdx.z;
    const int kc = g_kcnt[sig];
    const int pad = (kc + KTILE - 1) & ~(KTILE - 1);
    const int jc = blockIdx.x * 32 + threadIdx.x / 10;
    const int c4 = threadIdx.x % 10;
    if (jc >= pad) return;

    size_t dst = ((size_t)((sig - 1) * HEADS + head) * NTOK + jc) * DH + c4 * 4;
    float4 kv = make_float4(0.f, 0.f, 0.f, 0.f);
    float4 vv = make_float4(0.f, 0.f, 0.f, 0.f);
    if (jc < kc) {
        int j = g_kidx[sig][jc];
        size_t src = ((size_t)head * NTOK + j) * DH + c4 * 4;
        kv = *(const float4*)(g_k + src);
        vv = *(const float4*)(g_v + src);
    }
    *(float4*)(g_kc + dst) = kv;
    *(float4*)(g_vc + dst) = vv;
}

// ---------------------------------------------------------------------------
// Per-head V column mean (for fully-masked rows)
// ---------------------------------------------------------------------------
__global__ __launch_bounds__(320) void meanv_kernel() {
    __shared__ float red[320];
    const int head = blockIdx.x;
    const int t = threadIdx.x;
    const int d = t % DH, r = t / DH;
    float s = 0.0f;
    for (int j = r; j < NTOK; j += 8)
        s += g_v[((size_t)head * NTOK + j) * DH + d];
    red[t] = s;
    __syncthreads();
    if (r == 0) {
        float tot = 0.0f;
        #pragma unroll
        for (int rr = 0; rr < 8; rr++) tot += red[rr * DH + d];
        g_meanv[head * DH + d] = tot * (1.0f / (float)NTOK);
    }
}

// ---------------------------------------------------------------------------
// Flash attention over uniform work units (unchanged from R9).
// 128 threads = 64 queries x 2 dim-halves; f32x2 math, log2 softmax.
// ---------------------------------------------------------------------------
__global__ __launch_bounds__(128) void attn_kernel() {
    if (blockIdx.x >= g_nunits) return;
    __shared__ __align__(16) float ksh[KTILE * DH];
    __shared__ __align__(16) float vsh[KTILE * DH];

    const int tid  = threadIdx.x;
    const int head = blockIdx.y;
    const int uix  = blockIdx.x;
    const int sig  = g_u_sig[uix];
    const int qoff = g_u_qoff[uix];
    const int qend = g_u_qend[uix];
    const int t_start = g_u_t0[uix];
    const int t_end   = g_u_t1[uix];
    const int spl  = g_u_spl[uix];
    const int q    = tid >> 1;
    const int half = tid & 1;
    const int ql   = qoff + q;
    const bool vq  = ql < qend;
    const int qi   = g_qidx[vq ? ql : qoff];
    const float scale = 0.15811388300841898f * 1.4426950408889634f;

    const float* Kb = g_kc + (size_t)((sig - 1) * HEADS + head) * NTOK * DH;
    const float* Vb = g_vc + (size_t)((sig - 1) * HEADS + head) * NTOK * DH;

    ull q2[10];
    {
        const float4* qp = (const float4*)(g_q + ((size_t)head * NTOK + qi) * DH + half * 20);
        #pragma unroll
        for (int i = 0; i < 5; i++) {
            float4 v = qp[i];
            PACK2(q2[2 * i + 0], v.x * scale, v.y * scale);
            PACK2(q2[2 * i + 1], v.z * scale, v.w * scale);
        }
    }

    float m = -FLT_MAX, l = 0.0f;
    ull acc2[10];
    #pragma unroll
    for (int d = 0; d < 10; d++) acc2[d] = 0ull;

    for (int t0 = t_start; t0 < t_end; t0 += KTILE) {
        __syncthreads();
        const float4* kg = (const float4*)(Kb + (size_t)t0 * DH);
        const float4* vg = (const float4*)(Vb + (size_t)t0 * DH);
        float4* ks4 = (float4*)ksh;
        float4* vs4 = (float4*)vsh;
        #pragma unroll
        for (int i = tid; i < KTILE * DH / 4; i += 128) {
            ks4[i] = kg[i];
            vs4[i] = vg[i];
        }
        __syncthreads();

        const int lim = (t_end - t0 < KTILE) ? (t_end - t0) : KTILE;
        for (int c = 0; c < lim; c += 16) {
            float s[16];
            float cmax = -FLT_MAX;
            #pragma unroll
            for (int j = 0; j < 16; j++) {
                const ulonglong2* kr =
                    (const ulonglong2*)(ksh + (c + j) * DH + half * 20);
                ull sva = 0ull, svb = 0ull;
                ulonglong2 k0 = kr[0], k1 = kr[1], k2 = kr[2], k3 = kr[3], k4 = kr[4];
                FMA2(sva, q2[0], k0.x, sva);
                FMA2(svb, q2[1], k0.y, svb);
                FMA2(sva, q2[2], k1.x, sva);
                FMA2(svb, q2[3], k1.y, svb);
                FMA2(sva, q2[4], k2.x, sva);
                FMA2(svb, q2[5], k2.y, svb);
                FMA2(sva, q2[6], k3.x, sva);
                FMA2(svb, q2[7], k3.y, svb);
                FMA2(sva, q2[8], k4.x, sva);
                FMA2(svb, q2[9], k4.y, svb);
                float la, ha, lb, hb;
                UNPACK2(la, ha, sva);
                UNPACK2(lb, hb, svb);
                float svf = (la + ha) + (lb + hb);
                svf += __shfl_xor_sync(0xffffffffu, svf, 1);
                s[j] = (c + j < lim) ? svf : -FLT_MAX;
                cmax = fmaxf(cmax, s[j]);
            }
            float mnew = fmaxf(m, cmax);
            float corr = ex2(m - mnew);
            l *= corr;
            {
                ull corr2;
                PACK2(corr2, corr, corr);
                #pragma unroll
                for (int d = 0; d < 10; d++) MUL2(acc2[d], acc2[d], corr2);
            }
            #pragma unroll
            for (int j = 0; j < 16; j++) {
                float pj = ex2(s[j] - mnew);
                l += pj;
                ull pj2;
                PACK2(pj2, pj, pj);
                const ulonglong2* vr =
                    (const ulonglong2*)(vsh + (c + j) * DH + half * 20);
                ulonglong2 v0 = vr[0], v1 = vr[1], v2 = vr[2], v3 = vr[3], v4 = vr[4];
                FMA2(acc2[0], pj2, v0.x, acc2[0]);
                FMA2(acc2[1], pj2, v0.y, acc2[1]);
                FMA2(acc2[2], pj2, v1.x, acc2[2]);
                FMA2(acc2[3], pj2, v1.y, acc2[3]);
                FMA2(acc2[4], pj2, v2.x, acc2[4]);
                FMA2(acc2[5], pj2, v2.y, acc2[5]);
                FMA2(acc2[6], pj2, v3.x, acc2[6]);
                FMA2(acc2[7], pj2, v3.y, acc2[7]);
                FMA2(acc2[8], pj2, v4.x, acc2[8]);
                FMA2(acc2[9], pj2, v4.y, acc2[9]);
            }
            m = mnew;
        }
    }

    if (vq) {
        size_t base = (size_t)(spl * HEADS + head) * NTOK + ql;
        if (half == 0) {
            g_pm[base] = m;
            g_pl[base] = l;
        }
        float4* pp = (float4*)(g_pacc + base * DH + half * 20);
        #pragma unroll
        for (int d4 = 0; d4 < 5; d4++) {
            float4 r;
            UNPACK2(r.x, r.y, acc2[2 * d4 + 0]);
            UNPACK2(r.z, r.w, acc2[2 * d4 + 1]);
            pp[d4] = r;
        }
    }
}

// ---------------------------------------------------------------------------
// Merge split partials AND fill fully-masked rows with meanV (fused).
// One thread per (ql, head) over all NTOK queries.
// ---------------------------------------------------------------------------
__global__ __launch_bounds__(256) void reduce_kernel() {
    const int idx = blockIdx.x * 256 + threadIdx.x;
    if (idx >= NTOK * HEADS) return;
    const int ql = idx / HEADS;
    const int head = idx % HEADS;
    const int nq0 = g_grp_cnt[0];
    const int qi = g_qidx[ql];
    float* op = g_o + (size_t)qi * DMODEL + head * DH;

    if (ql < nq0) {
        // fully-masked query: uniform softmax -> mean of V
        const float4* mv = (const float4*)(g_meanv + head * DH);
        #pragma unroll
        for (int d4 = 0; d4 < 10; d4++) *(float4*)(op + d4 * 4) = mv[d4];
        return;
    }

    int sig = 1;
    #pragma unroll
    for (int s = 2; s < 8; s++)
        if (ql >= g_grp_off[s]) sig = s;
    const int ns = g_nsplit[sig];

    float m = -FLT_MAX;
    for (int s = 0; s < ns; s++) {
        float ms = g_pm[(size_t)(s * HEADS + head) * NTOK + ql];
        m = fmaxf(m, ms);
    }
    float l = 0.0f;
    for (int s = 0; s < ns; s++) {
        size_t base = (size_t)(s * HEADS + head) * NTOK + ql;
        l += g_pl[base] * ex2(g_pm[base] - m);
    }
    const float inv = 1.0f / l;

    float sum[DH];
    #pragma unroll
    for (int d = 0; d < DH; d++) sum[d] = 0.0f;
    for (int s = 0; s < ns; s++) {
        size_t base = (size_t)(s * HEADS + head) * NTOK + ql;
        float w = ex2(g_pm[base] - m);
        const float4* pa = (const float4*)(g_pacc + base * DH);
        #pragma unroll
        for (int d4 = 0; d4 < 10; d4++) {
            float4 a = pa[d4];
            sum[d4 * 4 + 0] += w * a.x;
            sum[d4 * 4 + 1] += w * a.y;
            sum[d4 * 4 + 2] += w * a.z;
            sum[d4 * 4 + 3] += w * a.w;
        }
    }
    #pragma unroll
    for (int d4 = 0; d4 < 10; d4++) {
        float4 r;
        r.x = sum[d4 * 4 + 0] * inv;
        r.y = sum[d4 * 4 + 1] * inv;
        r.z = sum[d4 * 4 + 2] * inv;
        r.w = sum[d4 * 4 + 3] * inv;
        *(float4*)(op + d4 * 4) = r;
    }
}

// ---------------------------------------------------------------------------
// Output projection: g_o(4096x320) @ Wo + bo -> d_out. 128x64, f32x2 packed.
// ---------------------------------------------------------------------------
__global__ __launch_bounds__(256) void out_gemm(
    const float* __restrict__ Wo, const float* __restrict__ bo,
    float* __restrict__ out)
{
    __shared__ float As[16][128];
    __shared__ float Bs[16][64];

    const int tid = threadIdx.x;
    const int m0 = blockIdx.y * 128;
    const int n0 = blockIdx.x * 64;
    const int tx = tid % 16, ty = tid / 16;
    const int ar = tid / 4,  ac = (tid % 4) * 4;
    const int br = tid / 16, bc = (tid % 16) * 4;

    ull acc2[4][4];
    #pragma unroll
    for (int i = 0; i < 4; i++)
        #pragma unroll
        for (int j = 0; j < 4; j++) acc2[i][j] = 0ull;

    for (int k0 = 0; k0 < DMODEL; k0 += 16) {
        float4 a0 = *(const float4*)(g_o + (size_t)(m0 + ar) * DMODEL + k0 + ac);
        float4 a1 = *(const float4*)(g_o + (size_t)(m0 + ar + 64) * DMODEL + k0 + ac);
        float4 bv = *(const float4*)(Wo + (size_t)(k0 + br) * DMODEL + n0 + bc);
        __syncthreads();
        As[ac + 0][ar] = a0.x; As[ac + 1][ar] = a0.y;
        As[ac + 2][ar] = a0.z; As[ac + 3][ar] = a0.w;
        As[ac + 0][ar + 64] = a1.x; As[ac + 1][ar + 64] = a1.y;
        As[ac + 2][ar + 64] = a1.z; As[ac + 3][ar + 64] = a1.w;
        *(float4*)&Bs[br][bc] = bv;
        __syncthreads();
        #pragma unroll
        for (int kk = 0; kk < 16; kk++) {
            ulonglong2 ap0 = *(const ulonglong2*)&As[kk][ty * 8];
            ulonglong2 ap1 = *(const ulonglong2*)&As[kk][ty * 8 + 4];
            float4 b = *(const float4*)&Bs[kk][tx * 4];
            ull bb[4];
            PACK2(bb[0], b.x, b.x);
            PACK2(bb[1], b.y, b.y);
            PACK2(bb[2], b.z, b.z);
            PACK2(bb[3], b.w, b.w);
            ull ap[4] = {ap0.x, ap0.y, ap1.x, ap1.y};
            #pragma unroll
            for (int rp = 0; rp < 4; rp++)
                #pragma unroll
                for (int j = 0; j < 4; j++)
                    FMA2(acc2[rp][j], ap[rp], bb[j], acc2[rp][j]);
        }
    }

    float4 bias = *(const float4*)(bo + n0 + tx * 4);
    float bias_a[4] = {bias.x, bias.y, bias.z, bias.w};
    #pragma unroll
    for (int rp = 0; rp < 4; rp++) {
        int tok = m0 + ty * 8 + rp * 2;
        float4 r0, r1;
        float lo, hi;
        UNPACK2(lo, hi, acc2[rp][0]); r0.x = lo + bias_a[0]; r1.x = hi + bias_a[0];
        UNPACK2(lo, hi, acc2[rp][1]); r0.y = lo + bias_a[1]; r1.y = hi + bias_a[1];
        UNPACK2(lo, hi, acc2[rp][2]); r0.z = lo + bias_a[2]; r1.z = hi + bias_a[2];
        UNPACK2(lo, hi, acc2[rp][3]); r0.w = lo + bias_a[3]; r1.w = hi + bias_a[3];
        *(float4*)(out + (size_t)tok * DMODEL + n0 + tx * 4) = r0;
        *(float4*)(out + (size_t)(tok + 1) * DMODEL + n0 + tx * 4) = r1;
    }
}

// ---------------------------------------------------------------------------
extern "C" void kernel_launch(void* const* d_in, const int* in_sizes, int n_in,
                              void* d_out, int out_size)
{
    const float* x  = (const float*)d_in[0];
    const float* gm = (const float*)d_in[1];
    const float* Wq = (const float*)d_in[2];
    const float* Wk = (const float*)d_in[3];
    const float* Wv = (const float*)d_in[4];
    const float* Wo = (const float*)d_in[5];
    const float* bo = (const float*)d_in[6];
    float* out = (float*)d_out;

    plan_kernel<<<1, 256>>>(gm);

    dim3 gq(DMODEL / 64, NTOK / 128, 3);
    qkv_gemm<<<gq, 256>>>(x, Wq, Wk, Wv);

    dim3 gg(128, 7, HEADS);
    gather_kernel<<<gg, 320>>>();

    meanv_kernel<<<HEADS, 320>>>();

    dim3 ga(MAXU, HEADS);
    attn_kernel<<<ga, 128>>>();

    reduce_kernel<<<(NTOK * HEADS + 255) / 256, 256>>>();

    dim3 go(DMODEL / 64, NTOK / 128);
    out_gemm<<<go, 256>>>(Wo, bo, out);
}